// round 12
// baseline (speedup 1.0000x reference)
#include <cuda_runtime.h>
#include <cuda_bf16.h>
#include <cstdint>

#define EMB   1024
#define HEADS 16
#define HD    64
#define BATCH 4
#define SEQ   2048
#define NROWS (BATCH * SEQ)      // 8192
#define QKVW  (3 * EMB)          // 3072

// ---------------------------------------------------------------------------
// Global scratch: split-bf16 planes
// ---------------------------------------------------------------------------
__device__ __align__(128) uint16_t g_x_hi[(size_t)NROWS * EMB];
__device__ __align__(128) uint16_t g_x_lo[(size_t)NROWS * EMB];
__device__ __align__(128) uint16_t g_wqkv_hi[(size_t)EMB * QKVW];
__device__ __align__(128) uint16_t g_wqkv_lo[(size_t)EMB * QKVW];
__device__ __align__(128) uint16_t g_wout_hi[(size_t)EMB * EMB];
__device__ __align__(128) uint16_t g_wout_lo[(size_t)EMB * EMB];
__device__ __align__(128) uint16_t g_qkv_hi[(size_t)NROWS * QKVW];
__device__ __align__(128) uint16_t g_qkv_lo[(size_t)NROWS * QKVW];
__device__ __align__(128) uint16_t g_attn_hi[(size_t)NROWS * EMB];
__device__ __align__(128) uint16_t g_attn_lo[(size_t)NROWS * EMB];

// ---------------------------------------------------------------------------
// Helpers
// ---------------------------------------------------------------------------
__device__ __forceinline__ uint32_t smem_u32(const void* p) {
    uint32_t a;
    asm("{ .reg .u64 t; cvta.to.shared.u64 t, %1; cvt.u32.u64 %0, t; }"
        : "=r"(a) : "l"(p));
    return a;
}
__device__ __forceinline__ void split_pair(float2 v, uint32_t& hi, uint32_t& lo) {
    uint32_t ax = __float_as_uint(v.x), bx = __float_as_uint(v.y);
    hi = __byte_perm(ax, bx, 0x7632);
    float lx = v.x - __uint_as_float(ax & 0xFFFF0000u);
    float ly = v.y - __uint_as_float(bx & 0xFFFF0000u);
    asm("cvt.rn.bf16x2.f32 %0, %1, %2;" : "=r"(lo) : "f"(ly), "f"(lx));
}
__device__ __forceinline__ void ldsm_x4(uint32_t* r, uint32_t addr) {
    asm volatile("ldmatrix.sync.aligned.m8n8.x4.shared.b16 {%0,%1,%2,%3}, [%4];"
                 : "=r"(r[0]), "=r"(r[1]), "=r"(r[2]), "=r"(r[3]) : "r"(addr));
}
__device__ __forceinline__ void ldsm_x4_t(uint32_t* r, uint32_t addr) {
    asm volatile("ldmatrix.sync.aligned.m8n8.x4.trans.shared.b16 {%0,%1,%2,%3}, [%4];"
                 : "=r"(r[0]), "=r"(r[1]), "=r"(r[2]), "=r"(r[3]) : "r"(addr));
}
__device__ __forceinline__ void mma_bf16(float* c, const uint32_t* a,
                                         const uint32_t* b) {
    asm volatile(
        "mma.sync.aligned.m16n8k16.row.col.f32.bf16.bf16.f32 "
        "{%0,%1,%2,%3}, {%4,%5,%6,%7}, {%8,%9}, {%0,%1,%2,%3};"
        : "+f"(c[0]), "+f"(c[1]), "+f"(c[2]), "+f"(c[3])
        : "r"(a[0]), "r"(a[1]), "r"(a[2]), "r"(a[3]), "r"(b[0]), "r"(b[1]));
}
__device__ __forceinline__ void cp16(uint32_t s, const void* g) {
    asm volatile("cp.async.cg.shared.global [%0], [%1], 16;" :: "r"(s), "l"(g));
}
__device__ __forceinline__ void cp_commit() {
    asm volatile("cp.async.commit_group;");
}
template<int N> __device__ __forceinline__ void cp_wait() {
    asm volatile("cp.async.wait_group %0;" :: "n"(N));
}

// ---------------------------------------------------------------------------
// fp32 -> split bf16 planes
// ---------------------------------------------------------------------------
__global__ void split_kernel(const float4* __restrict__ src,
                             uint16_t* __restrict__ hi,
                             uint16_t* __restrict__ lo, int n4)
{
    int i = blockIdx.x * blockDim.x + threadIdx.x;
    if (i >= n4) return;
    float4 v = src[i];
    uint32_t h0, l0, h1, l1;
    split_pair(make_float2(v.x, v.y), h0, l0);
    split_pair(make_float2(v.z, v.w), h1, l1);
    ((uint2*)hi)[i] = make_uint2(h0, h1);
    ((uint2*)lo)[i] = make_uint2(l0, l1);
}

// ===========================================================================
// GEMM v5 (QKV): high-intensity tile. Block 128m x 192n, 8 warps (2m x 4n),
// warp tile 64x48 (MT=4 m16, NT=6 n8), 96 acc regs. K-chunk 32, 2-stage
// cp.async, ONE __syncthreads per chunk. Writes split hi/lo planes with Q
// columns (n < qcols) pre-scaled by 0.125.
// Per-kc per-SM: 1152 HMMA (2304 tensor-cy @rt8) vs 224 ldsm (896 smem-cy)
// -> tensor-bound.
// A smem [128][40] (80B rows, 5x16B: conflict-free), B smem [32][200]
// (400B rows, 25x16B: conflict-free).
// ===========================================================================
#define H_OAH  0
#define H_OAL  10240
#define H_OBH  20480
#define H_OBL  33280
#define H_ST   46080
#define H_SMEM (2 * H_ST)   // 92160 (1 CTA/SM)

__global__ __launch_bounds__(256)
void gemm_tc3(const uint16_t* __restrict__ Ah, const uint16_t* __restrict__ Al,
              const uint16_t* __restrict__ Bh, const uint16_t* __restrict__ Bl,
              const float* __restrict__ bias,
              uint16_t* __restrict__ Ch, uint16_t* __restrict__ Cl,
              int N, int K, int qcols)
{
    extern __shared__ char sm[];
    const uint32_t sbase = smem_u32(sm);

    const int tid  = threadIdx.x;
    const int lane = tid & 31;
    const int wid  = tid >> 5;
    const int wm   = wid & 1;           // 0..1 -> 64 rows each
    const int wn   = wid >> 1;          // 0..3 -> 48 cols each
    const int row0 = blockIdx.y * 128;
    const int col0 = blockIdx.x * 192;

    // loaders: A 128 rows x 32 k (2 thr/row, 2x16B each per plane)
    const int ar = tid >> 1;
    const uint16_t* Aph = Ah + (size_t)(row0 + ar) * K + (tid & 1) * 16;
    const uint16_t* Apl = Al + (size_t)(row0 + ar) * K + (tid & 1) * 16;
    const uint32_t sao = (uint32_t)(ar * 80 + (tid & 1) * 32);
    // loaders: B 32 k-rows x 192 (8 thr/row, 3x16B each per plane)
    const int br = tid >> 3;
    const uint16_t* Bph = Bh + (size_t)br * N + col0 + (tid & 7) * 8;
    const uint16_t* Bpl = Bl + (size_t)br * N + col0 + (tid & 7) * 8;
    const uint32_t sbo = (uint32_t)(br * 400 + (tid & 7) * 16);

    // per-lane ldmatrix bases
    const int g  = lane >> 3;
    const int rr = lane & 7;
    uint32_t abase[4];
    #pragma unroll
    for (int mt = 0; mt < 4; mt++)
        abase[mt] = (uint32_t)((wm * 64 + mt * 16 + (g & 1) * 8 + rr) * 40
                               + (g >> 1) * 8) * 2u;
    uint32_t bbase[3];
    #pragma unroll
    for (int p = 0; p < 3; p++)
        bbase[p] = (uint32_t)(((g & 1) * 8 + rr) * 200
                              + wn * 48 + p * 16 + (g >> 1) * 8) * 2u;

    float acc[4][6][4];
    #pragma unroll
    for (int i = 0; i < 4; i++)
        #pragma unroll
        for (int j = 0; j < 6; j++)
            #pragma unroll
            for (int r = 0; r < 4; r++)
                acc[i][j][r] = 0.f;

    auto LOAD = [&](int st, int k0) {
        uint32_t s0 = sbase + st * H_ST;
        cp16(s0 + H_OAH + sao,      Aph + k0);
        cp16(s0 + H_OAH + sao + 16, Aph + k0 + 8);
        cp16(s0 + H_OAL + sao,      Apl + k0);
        cp16(s0 + H_OAL + sao + 16, Apl + k0 + 8);
        const uint16_t* bh = Bph + (size_t)k0 * N;
        const uint16_t* bl = Bpl + (size_t)k0 * N;
        #pragma unroll
        for (int j = 0; j < 3; j++) {
            cp16(s0 + H_OBH + sbo + 128 * j, bh + 64 * j);
            cp16(s0 + H_OBL + sbo + 128 * j, bl + 64 * j);
        }
    };

    const int nk = K / 32;
    LOAD(0, 0);
    cp_commit();

    for (int kc = 0; kc < nk; kc++) {
        cp_wait<0>();
        __syncthreads();   // stage kc&1 ready; stage (kc+1)&1 fully consumed
        if (kc + 1 < nk) { LOAD((kc + 1) & 1, (kc + 1) * 32); cp_commit(); }

        uint32_t s0 = sbase + (kc & 1) * H_ST;
        #pragma unroll
        for (int ks = 0; ks < 2; ks++) {
            const uint32_t ka = ks * 32u;     // 16 elems * 2B
            const uint32_t kb = ks * 6400u;   // 16 rows * 400B
            uint32_t ahi[4][4], alo[4][4];
            #pragma unroll
            for (int mt = 0; mt < 4; mt++) {
                ldsm_x4(ahi[mt], s0 + H_OAH + abase[mt] + ka);
                ldsm_x4(alo[mt], s0 + H_OAL + abase[mt] + ka);
            }
            uint32_t bh[3][4], bl[3][4];
            #pragma unroll
            for (int p = 0; p < 3; p++) {
                ldsm_x4_t(bh[p], s0 + H_OBH + bbase[p] + kb);
                ldsm_x4_t(bl[p], s0 + H_OBL + bbase[p] + kb);
            }
            // term 1: Ahi*Bhi (24 distinct accumulators)
            #pragma unroll
            for (int p = 0; p < 3; p++)
                #pragma unroll
                for (int mt = 0; mt < 4; mt++) {
                    mma_bf16(acc[mt][2 * p + 0], ahi[mt], bh[p]);
                    mma_bf16(acc[mt][2 * p + 1], ahi[mt], bh[p] + 2);
                }
            // term 2: Ahi*Blo
            #pragma unroll
            for (int p = 0; p < 3; p++)
                #pragma unroll
                for (int mt = 0; mt < 4; mt++) {
                    mma_bf16(acc[mt][2 * p + 0], ahi[mt], bl[p]);
                    mma_bf16(acc[mt][2 * p + 1], ahi[mt], bl[p] + 2);
                }
            // term 3: Alo*Bhi
            #pragma unroll
            for (int p = 0; p < 3; p++)
                #pragma unroll
                for (int mt = 0; mt < 4; mt++) {
                    mma_bf16(acc[mt][2 * p + 0], alo[mt], bh[p]);
                    mma_bf16(acc[mt][2 * p + 1], alo[mt], bh[p] + 2);
                }
        }
        // single barrier per chunk: next iteration's sync protects reuse
    }

    // ---- epilogue: split-plane writes (Q pre-scale folded) ----
    const int ml = lane >> 2;
    const int nl = 2 * (lane & 3);
    #pragma unroll
    for (int mt = 0; mt < 4; mt++) {
        #pragma unroll
        for (int nt = 0; nt < 6; nt++) {
            int m = row0 + wm * 64 + mt * 16 + ml;
            int n = col0 + wn * 48 + nt * 8 + nl;
            float2 bv = *(const float2*)&bias[n];
            float* c = acc[mt][nt];
            float sc = (n < qcols) ? 0.125f : 1.0f;
            float v0 = (c[0] + bv.x) * sc, v1 = (c[1] + bv.y) * sc;
            float w0 = (c[2] + bv.x) * sc, w1 = (c[3] + bv.y) * sc;
            uint32_t h, l;
            split_pair(make_float2(v0, v1), h, l);
            *(uint32_t*)(Ch + (size_t)m * N + n) = h;
            *(uint32_t*)(Cl + (size_t)m * N + n) = l;
            split_pair(make_float2(w0, w1), h, l);
            *(uint32_t*)(Ch + (size_t)(m + 8) * N + n) = h;
            *(uint32_t*)(Cl + (size_t)(m + 8) * N + n) = l;
        }
    }
}

// ===========================================================================
// GEMM v4 (out-proj, unchanged from R11): 128x128, 2-stage, 2 CTAs/SM.
// ===========================================================================
#define G_OAH  0
#define G_OAL  10240
#define G_OBH  20480
#define G_OBL  29184
#define G_ST   37888
#define G_SMEM (2 * G_ST)

__global__ __launch_bounds__(256, 2)
void gemm_tc2(const uint16_t* __restrict__ Ah, const uint16_t* __restrict__ Al,
              const uint16_t* __restrict__ Bh, const uint16_t* __restrict__ Bl,
              const float* __restrict__ bias, float* __restrict__ Cf,
              int N, int K)
{
    extern __shared__ char sm[];
    const uint32_t sbase = smem_u32(sm);

    const int tid  = threadIdx.x;
    const int lane = tid & 31;
    const int wid  = tid >> 5;
    const int wm   = wid & 3;
    const int wn   = wid >> 2;
    const int row0 = blockIdx.y * 128;
    const int col0 = blockIdx.x * 128;

    const int ar  = tid >> 1;
    const int akc = (tid & 1) * 2;
    const int br  = tid >> 3;
    const int bnc = (tid & 7) * 2;

    const uint16_t* Aph = Ah + (size_t)(row0 + ar) * K + akc * 8;
    const uint16_t* Apl = Al + (size_t)(row0 + ar) * K + akc * 8;
    const uint16_t* Bph = Bh + (size_t)br * N + col0 + bnc * 8;
    const uint16_t* Bpl = Bl + (size_t)br * N + col0 + bnc * 8;

    const uint32_t sao0 = (uint32_t)(ar * 40 + akc * 8) * 2u;
    const uint32_t sao1 = sao0 + 16u;
    const uint32_t sbo0 = (uint32_t)(br * 136 + bnc * 8) * 2u;
    const uint32_t sbo1 = sbo0 + 16u;

    const int g  = lane >> 3;
    const int rr = lane & 7;
    uint32_t abase[2];
    #pragma unroll
    for (int mt = 0; mt < 2; mt++)
        abase[mt] = (uint32_t)((wm * 32 + mt * 16 + (g & 1) * 8 + rr) * 40
                               + (g >> 1) * 8) * 2u;
    uint32_t bbase[4];
    #pragma unroll
    for (int np = 0; np < 4; np++)
        bbase[np] = (uint32_t)(((g & 1) * 8 + rr) * 136
                               + wn * 64 + np * 16 + (g >> 1) * 8) * 2u;

    float acc[2][8][4];
    #pragma unroll
    for (int i = 0; i < 2; i++)
        #pragma unroll
        for (int j = 0; j < 8; j++)
            #pragma unroll
            for (int r = 0; r < 4; r++)
                acc[i][j][r] = 0.f;

    auto LOAD = [&](int st, int k0) {
        uint32_t s0 = sbase + st * G_ST;
        cp16(s0 + G_OAH + sao0, Aph + k0);
        cp16(s0 + G_OAH + sao1, Aph + k0 + 8);
        cp16(s0 + G_OAL + sao0, Apl + k0);
        cp16(s0 + G_OAL + sao1, Apl + k0 + 8);
        cp16(s0 + G_OBH + sbo0, Bph + (size_t)k0 * N);
        cp16(s0 + G_OBH + sbo1, Bph + (size_t)k0 * N + 8);
        cp16(s0 + G_OBL + sbo0, Bpl + (size_t)k0 * N);
        cp16(s0 + G_OBL + sbo1, Bpl + (size_t)k0 * N + 8);
    };

    const int nk = K / 32;
    LOAD(0, 0);  cp_commit();
    LOAD(1, 32); cp_commit();

    for (int kc = 0; kc < nk; kc++) {
        if (kc < nk - 1) cp_wait<1>();
        else             cp_wait<0>();
        __syncthreads();

        uint32_t s0 = sbase + (kc & 1) * G_ST;
        #pragma unroll
        for (int ks = 0; ks < 2; ks++) {
            const uint32_t ka = ks * 32u;
            const uint32_t kb = ks * 4352u;
            uint32_t ahi[2][4], alo[2][4];
            ldsm_x4(ahi[0], s0 + G_OAH + abase[0] + ka);
            ldsm_x4(ahi[1], s0 + G_OAH + abase[1] + ka);
            ldsm_x4(alo[0], s0 + G_OAL + abase[0] + ka);
            ldsm_x4(alo[1], s0 + G_OAL + abase[1] + ka);
            #pragma unroll
            for (int nph = 0; nph < 2; nph++) {
                uint32_t bh[2][4], bl[2][4];
                ldsm_x4_t(bh[0], s0 + G_OBH + bbase[2 * nph + 0] + kb);
                ldsm_x4_t(bl[0], s0 + G_OBL + bbase[2 * nph + 0] + kb);
                ldsm_x4_t(bh[1], s0 + G_OBH + bbase[2 * nph + 1] + kb);
                ldsm_x4_t(bl[1], s0 + G_OBL + bbase[2 * nph + 1] + kb);
                #pragma unroll
                for (int p = 0; p < 2; p++)
                    #pragma unroll
                    for (int mt = 0; mt < 2; mt++) {
                        mma_bf16(acc[mt][4 * nph + 2 * p + 0], ahi[mt], bh[p]);
                        mma_bf16(acc[mt][4 * nph + 2 * p + 1], ahi[mt], bh[p] + 2);
                    }
                #pragma unroll
                for (int p = 0; p < 2; p++)
                    #pragma unroll
                    for (int mt = 0; mt < 2; mt++) {
                        mma_bf16(acc[mt][4 * nph + 2 * p + 0], ahi[mt], bl[p]);
                        mma_bf16(acc[mt][4 * nph + 2 * p + 1], ahi[mt], bl[p] + 2);
                    }
                #pragma unroll
                for (int p = 0; p < 2; p++)
                    #pragma unroll
                    for (int mt = 0; mt < 2; mt++) {
                        mma_bf16(acc[mt][4 * nph + 2 * p + 0], alo[mt], bh[p]);
                        mma_bf16(acc[mt][4 * nph + 2 * p + 1], alo[mt], bh[p] + 2);
                    }
            }
        }
        __syncthreads();
        if (kc + 2 < nk) { LOAD(kc & 1, (kc + 2) * 32); cp_commit(); }
    }

    const int ml = lane >> 2;
    const int nl = 2 * (lane & 3);
    #pragma unroll
    for (int mt = 0; mt < 2; mt++) {
        #pragma unroll
        for (int nt = 0; nt < 8; nt++) {
            int m = row0 + wm * 32 + mt * 16 + ml;
            int n = col0 + wn * 64 + nt * 8 + nl;
            float2 bv = *(const float2*)&bias[n];
            float* c = acc[mt][nt];
            *(float2*)(Cf + (size_t)m * N + n) =
                make_float2(c[0] + bv.x, c[1] + bv.y);
            *(float2*)(Cf + (size_t)(m + 8) * N + n) =
                make_float2(c[2] + bv.x, c[3] + bv.y);
        }
    }
}

// ===========================================================================
// Flash attention (unchanged from R11): term-major + cp.async double buffer.
// ===========================================================================
#define FA_PAD  72
#define O_QHI   0
#define O_QLO   18432
#define KV_ST0  36864
#define P_KHI   0
#define P_KLO   9216
#define P_VHI   18432
#define P_VLO   27648
#define KV_STG  36864
#define FA_SMEM (KV_ST0 + 2 * KV_STG)   // 110592

__global__ __launch_bounds__(256)
void flash_attn_mma_kernel(const uint16_t* __restrict__ qkv_hi,
                           const uint16_t* __restrict__ qkv_lo,
                           uint16_t* __restrict__ attn_hi,
                           uint16_t* __restrict__ attn_lo)
{
    extern __shared__ char fsm[];
    const uint32_t sb = smem_u32(fsm);

    const int tid  = threadIdx.x;
    const int lane = tid & 31;
    const int wm   = tid >> 5;
    const int qt   = blockIdx.x;
    const int b    = blockIdx.y >> 4;
    const int h    = blockIdx.y & 15;

    {
        const int r  = tid >> 1;
        const int c0 = (tid & 1) * 32;
        const uint16_t* qh = qkv_hi + (size_t)(b * SEQ + qt * 128 + r) * QKVW
                                    + h * HD + c0;
        const uint16_t* ql = qkv_lo + (size_t)(b * SEQ + qt * 128 + r) * QKVW
                                    + h * HD + c0;
        uint32_t base = (uint32_t)(r * FA_PAD + c0) * 2u;
        #pragma unroll
        for (int s = 0; s < 4; s++) {
            *(uint4*)(fsm + O_QHI + base + 16 * s) = *(const uint4*)(qh + 8 * s);
            *(uint4*)(fsm + O_QLO + base + 16 * s) = *(const uint4*)(ql + 8 * s);
        }
    }

    const int kr  = tid >> 2;
    const int kc0 = (tid & 3) * 16;
    auto LOADKV = [&](int kt, int st) {
        size_t roff = (size_t)(b * SEQ + kt * 64 + kr) * QKVW + h * HD + kc0;
        const uint16_t* gh = qkv_hi + roff;
        const uint16_t* gl = qkv_lo + roff;
        uint32_t d = sb + KV_ST0 + (uint32_t)(st * KV_STG)
                   + (uint32_t)(kr * FA_PAD + kc0) * 2u;
        cp16(d + P_KHI,      gh + EMB);
        cp16(d + P_KHI + 16, gh + EMB + 8);
        cp16(d + P_KLO,      gl + EMB);
        cp16(d + P_KLO + 16, gl + EMB + 8);
        cp16(d + P_VHI,      gh + 2 * EMB);
        cp16(d + P_VHI + 16, gh + 2 * EMB + 8);
        cp16(d + P_VLO,      gl + 2 * EMB);
        cp16(d + P_VLO + 16, gl + 2 * EMB + 8);
    };

    LOADKV(0, 0);
    cp_commit();
    __syncthreads();

    const int g  = lane >> 3;
    const int rr = lane & 7;
    uint32_t qhi[4][4], qlo[4][4];
    {
        uint32_t moff = (uint32_t)((wm * 16 + (g & 1) * 8 + rr) * FA_PAD) * 2u;
        #pragma unroll
        for (int t = 0; t < 4; t++) {
            uint32_t koff = (uint32_t)((g >> 1) * 8 + 16 * t) * 2u;
            ldsm_x4(qhi[t], sb + O_QHI + moff + koff);
            ldsm_x4(qlo[t], sb + O_QLO + moff + koff);
        }
    }

    const uint32_t kbase = (uint32_t)(((g >> 1) * 8 + rr) * FA_PAD + (g & 1) * 8) * 2u;
    const uint32_t vbase = (uint32_t)(((g & 1) * 8 + rr) * FA_PAD + (g >> 1) * 8) * 2u;

    float m0 = -1e30f, m1 = -1e30f, l0 = 0.f, l1 = 0.f;
    float o[8][4];
    #pragma unroll
    for (int j = 0; j < 8; j++)
        #pragma unroll
        for (int r = 0; r < 4; r++) o[j][r] = 0.f;

    for (int kt = 0; kt < SEQ / 64; kt++) {
        cp_wait<0>();
        __syncthreads();
        if (kt + 1 < SEQ / 64) { LOADKV(kt + 1, (kt + 1) & 1); cp_commit(); }

        const uint32_t stg = sb + KV_ST0 + (uint32_t)((kt & 1) * KV_STG);

        float s[8][4];
        #pragma unroll
        for (int j = 0; j < 8; j++)
            #pragma unroll
            for (int r4 = 0; r4 < 4; r4++) s[j][r4] = 0.f;

        #pragma unroll
        for (int t = 0; t < 4; t++) {
            uint32_t kfh[4][4], kfl[4][4];
            #pragma unroll
            for (int nt = 0; nt < 4; nt++) {
                uint32_t off = kbase + (uint32_t)(nt * 16 * FA_PAD + 16 * t) * 2u;
                ldsm_x4(kfh[nt], stg + P_KHI + off);
                ldsm_x4(kfl[nt], stg + P_KLO + off);
            }
            #pragma unroll
            for (int nt = 0; nt < 4; nt++) {
                mma_bf16(s[2 * nt + 0], qhi[t], kfh[nt]);
                mma_bf16(s[2 * nt + 1], qhi[t], kfh[nt] + 2);
            }
            #pragma unroll
            for (int nt = 0; nt < 4; nt++) {
                mma_bf16(s[2 * nt + 0], qhi[t], kfl[nt]);
                mma_bf16(s[2 * nt + 1], qhi[t], kfl[nt] + 2);
            }
            #pragma unroll
            for (int nt = 0; nt < 4; nt++) {
                mma_bf16(s[2 * nt + 0], qlo[t], kfh[nt]);
                mma_bf16(s[2 * nt + 1], qlo[t], kfh[nt] + 2);
            }
        }

        float mx0 = -1e30f, mx1 = -1e30f;
        #pragma unroll
        for (int j = 0; j < 8; j++) {
            mx0 = fmaxf(mx0, fmaxf(s[j][0], s[j][1]));
            mx1 = fmaxf(mx1, fmaxf(s[j][2], s[j][3]));
        }
        mx0 = fmaxf(mx0, __shfl_xor_sync(0xffffffffu, mx0, 1));
        mx0 = fmaxf(mx0, __shfl_xor_sync(0xffffffffu, mx0, 2));
        mx1 = fmaxf(mx1, __shfl_xor_sync(0xffffffffu, mx1, 1));
        mx1 = fmaxf(mx1, __shfl_xor_sync(0xffffffffu, mx1, 2));

        float mn0 = fmaxf(m0, mx0), mn1 = fmaxf(m1, mx1);
        float a0 = __expf(m0 - mn0), a1 = __expf(m1 - mn1);
        m0 = mn0; m1 = mn1;

        float sum0 = 0.f, sum1 = 0.f;
        #pragma unroll
        for (int j = 0; j < 8; j++) {
            s[j][0] = __expf(s[j][0] - mn0);
            s[j][1] = __expf(s[j][1] - mn0);
            s[j][2] = __expf(s[j][2] - mn1);
            s[j][3] = __expf(s[j][3] - mn1);
            sum0 += s[j][0] + s[j][1];
            sum1 += s[j][2] + s[j][3];
        }
        sum0 += __shfl_xor_sync(0xffffffffu, sum0, 1);
        sum0 += __shfl_xor_sync(0xffffffffu, sum0, 2);
        sum1 += __shfl_xor_sync(0xffffffffu, sum1, 1);
        sum1 += __shfl_xor_sync(0xffffffffu, sum1, 2);
        l0 = l0 * a0 + sum0;
        l1 = l1 * a1 + sum1;

        #pragma unroll
        for (int j = 0; j < 8; j++) {
            o[j][0] *= a0; o[j][1] *= a0;
            o[j][2] *= a1; o[j][3] *= a1;
        }

        #pragma unroll
        for (int t = 0; t < 4; t++) {
            uint32_t phi[4], plo[4];
            split_pair(make_float2(s[2*t][0],   s[2*t][1]),   phi[0], plo[0]);
            split_pair(make_float2(s[2*t][2],   s[2*t][3]),   phi[1], plo[1]);
            split_pair(make_float2(s[2*t+1][0], s[2*t+1][1]), phi[2], plo[2]);
            split_pair(make_float2(s[2*t+1][2], s[2*t+1][3]), phi[3], plo[3]);
            uint32_t vfh[4][4], vfl[4][4];
            #pragma unroll
            for (int nt = 0; nt < 4; nt++) {
                uint32_t off = vbase + (uint32_t)(t * 16 * FA_PAD + nt * 16) * 2u;
                ldsm_x4_t(vfh[nt], stg + P_VHI + off);
                ldsm_x4_t(vfl[nt], stg + P_VLO + off);
            }
            #pragma unroll
            for (int nt = 0; nt < 4; nt++) {
                mma_bf16(o[2 * nt + 0], phi, vfh[nt]);
                mma_bf16(o[2 * nt + 1], phi, vfh[nt] + 2);
            }
            #pragma unroll
            for (int nt = 0; nt < 4; nt++) {
                mma_bf16(o[2 * nt + 0], phi, vfl[nt]);
                mma_bf16(o[2 * nt + 1], phi, vfl[nt] + 2);
            }
            #pragma unroll
            for (int nt = 0; nt < 4; nt++) {
                mma_bf16(o[2 * nt + 0], plo, vfh[nt]);
                mma_bf16(o[2 * nt + 1], plo, vfh[nt] + 2);
            }
        }
    }

    float inv0 = 1.f / l0, inv1 = 1.f / l1;
    int row = b * SEQ + qt * 128 + wm * 16 + (lane >> 2);
    size_t e0 = (size_t)row * EMB + h * HD + 2 * (lane & 3);
    #pragma unroll
    for (int j = 0; j < 8; j++) {
        uint32_t hh, ll;
        split_pair(make_float2(o[j][0] * inv0, o[j][1] * inv0), hh, ll);
        *(uint32_t*)(attn_hi + e0 + 8 * j) = hh;
        *(uint32_t*)(attn_lo + e0 + 8 * j) = ll;
        split_pair(make_float2(o[j][2] * inv1, o[j][3] * inv1), hh, ll);
        *(uint32_t*)(attn_hi + e0 + (size_t)8 * EMB + 8 * j) = hh;
        *(uint32_t*)(attn_lo + e0 + (size_t)8 * EMB + 8 * j) = ll;
    }
}

// ---------------------------------------------------------------------------
extern "C" void kernel_launch(void* const* d_in, const int* in_sizes, int n_in,
                              void* d_out, int out_size)
{
    (void)in_sizes; (void)n_in; (void)out_size;
    const float* x     = (const float*)d_in[0];
    const float* w_qkv = (const float*)d_in[1];
    const float* b_qkv = (const float*)d_in[2];
    const float* w_out = (const float*)d_in[3];
    const float* b_out = (const float*)d_in[4];
    float* out = (float*)d_out;

    uint16_t *x_hi, *x_lo, *wq_hi, *wq_lo, *wo_hi, *wo_lo;
    uint16_t *qkv_hi, *qkv_lo, *attn_hi, *attn_lo;
    cudaGetSymbolAddress((void**)&x_hi,   g_x_hi);
    cudaGetSymbolAddress((void**)&x_lo,   g_x_lo);
    cudaGetSymbolAddress((void**)&wq_hi,  g_wqkv_hi);
    cudaGetSymbolAddress((void**)&wq_lo,  g_wqkv_lo);
    cudaGetSymbolAddress((void**)&wo_hi,  g_wout_hi);
    cudaGetSymbolAddress((void**)&wo_lo,  g_wout_lo);
    cudaGetSymbolAddress((void**)&qkv_hi, g_qkv_hi);
    cudaGetSymbolAddress((void**)&qkv_lo, g_qkv_lo);
    cudaGetSymbolAddress((void**)&attn_hi, g_attn_hi);
    cudaGetSymbolAddress((void**)&attn_lo, g_attn_lo);

    cudaFuncSetAttribute(gemm_tc3,
                         cudaFuncAttributeMaxDynamicSharedMemorySize, H_SMEM);
    cudaFuncSetAttribute(gemm_tc2,
                         cudaFuncAttributeMaxDynamicSharedMemorySize, G_SMEM);
    cudaFuncSetAttribute(flash_attn_mma_kernel,
                         cudaFuncAttributeMaxDynamicSharedMemorySize, FA_SMEM);

    // 0) one-shot splits
    split_kernel<<<(NROWS * EMB / 4) / 256, 256>>>(
        (const float4*)x, x_hi, x_lo, NROWS * EMB / 4);
    split_kernel<<<(EMB * QKVW / 4) / 256, 256>>>(
        (const float4*)w_qkv, wq_hi, wq_lo, EMB * QKVW / 4);
    split_kernel<<<(EMB * EMB / 4) / 256, 256>>>(
        (const float4*)w_out, wo_hi, wo_lo, EMB * EMB / 4);

    // 1) QKV projection (high-intensity tile) -> split planes
    gemm_tc3<<<dim3(QKVW / 192, NROWS / 128), 256, H_SMEM>>>(
        x_hi, x_lo, wq_hi, wq_lo, b_qkv, qkv_hi, qkv_lo, QKVW, EMB, EMB);

    // 2) attention -> split planes
    flash_attn_mma_kernel<<<dim3(SEQ / 128, BATCH * HEADS), 256, FA_SMEM>>>(
        qkv_hi, qkv_lo, attn_hi, attn_lo);

    // 3) output projection -> fp32 out
    gemm_tc2<<<dim3(EMB / 128, NROWS / 128), 256, G_SMEM>>>(
        attn_hi, attn_lo, wo_hi, wo_lo, b_out, out, EMB, EMB);
}

// round 13
// speedup vs baseline: 1.0039x; 1.0039x over previous
#include <cuda_runtime.h>
#include <cuda_bf16.h>
#include <cstdint>

#define EMB   1024
#define HEADS 16
#define HD    64
#define BATCH 4
#define SEQ   2048
#define NROWS (BATCH * SEQ)      // 8192
#define QKVW  (3 * EMB)          // 3072

// ---------------------------------------------------------------------------
// Global scratch: split-bf16 planes
// ---------------------------------------------------------------------------
__device__ __align__(128) uint16_t g_x_hi[(size_t)NROWS * EMB];
__device__ __align__(128) uint16_t g_x_lo[(size_t)NROWS * EMB];
__device__ __align__(128) uint16_t g_wqkv_hi[(size_t)EMB * QKVW];
__device__ __align__(128) uint16_t g_wqkv_lo[(size_t)EMB * QKVW];
__device__ __align__(128) uint16_t g_wout_hi[(size_t)EMB * EMB];
__device__ __align__(128) uint16_t g_wout_lo[(size_t)EMB * EMB];
__device__ __align__(128) uint16_t g_qkv_hi[(size_t)NROWS * QKVW];
__device__ __align__(128) uint16_t g_qkv_lo[(size_t)NROWS * QKVW];
__device__ __align__(128) uint16_t g_attn_hi[(size_t)NROWS * EMB];
__device__ __align__(128) uint16_t g_attn_lo[(size_t)NROWS * EMB];

// ---------------------------------------------------------------------------
// Helpers
// ---------------------------------------------------------------------------
__device__ __forceinline__ uint32_t smem_u32(const void* p) {
    uint32_t a;
    asm("{ .reg .u64 t; cvta.to.shared.u64 t, %1; cvt.u32.u64 %0, t; }"
        : "=r"(a) : "l"(p));
    return a;
}
__device__ __forceinline__ void split_pair(float2 v, uint32_t& hi, uint32_t& lo) {
    uint32_t ax = __float_as_uint(v.x), bx = __float_as_uint(v.y);
    hi = __byte_perm(ax, bx, 0x7632);
    float lx = v.x - __uint_as_float(ax & 0xFFFF0000u);
    float ly = v.y - __uint_as_float(bx & 0xFFFF0000u);
    asm("cvt.rn.bf16x2.f32 %0, %1, %2;" : "=r"(lo) : "f"(ly), "f"(lx));
}
__device__ __forceinline__ void ldsm_x4(uint32_t* r, uint32_t addr) {
    asm volatile("ldmatrix.sync.aligned.m8n8.x4.shared.b16 {%0,%1,%2,%3}, [%4];"
                 : "=r"(r[0]), "=r"(r[1]), "=r"(r[2]), "=r"(r[3]) : "r"(addr));
}
__device__ __forceinline__ void ldsm_x4_t(uint32_t* r, uint32_t addr) {
    asm volatile("ldmatrix.sync.aligned.m8n8.x4.trans.shared.b16 {%0,%1,%2,%3}, [%4];"
                 : "=r"(r[0]), "=r"(r[1]), "=r"(r[2]), "=r"(r[3]) : "r"(addr));
}
__device__ __forceinline__ void mma_bf16(float* c, const uint32_t* a,
                                         const uint32_t* b) {
    asm volatile(
        "mma.sync.aligned.m16n8k16.row.col.f32.bf16.bf16.f32 "
        "{%0,%1,%2,%3}, {%4,%5,%6,%7}, {%8,%9}, {%0,%1,%2,%3};"
        : "+f"(c[0]), "+f"(c[1]), "+f"(c[2]), "+f"(c[3])
        : "r"(a[0]), "r"(a[1]), "r"(a[2]), "r"(a[3]), "r"(b[0]), "r"(b[1]));
}
__device__ __forceinline__ void cp16(uint32_t s, const void* g) {
    asm volatile("cp.async.cg.shared.global [%0], [%1], 16;" :: "r"(s), "l"(g));
}
__device__ __forceinline__ void cp_commit() {
    asm volatile("cp.async.commit_group;");
}
template<int N> __device__ __forceinline__ void cp_wait() {
    asm volatile("cp.async.wait_group %0;" :: "n"(N));
}

// ---------------------------------------------------------------------------
// Merged fp32 -> split bf16 planes: one launch covers x, W_qkv, W_out.
// ---------------------------------------------------------------------------
#define N4_X  (NROWS * EMB / 4)      // 2097152
#define N4_WQ (EMB * QKVW / 4)       // 786432
#define N4_WO (EMB * EMB / 4)        // 262144

__global__ void split_all_kernel(const float4* __restrict__ x,
                                 const float4* __restrict__ wq,
                                 const float4* __restrict__ wo,
                                 uint16_t* __restrict__ x_hi,  uint16_t* __restrict__ x_lo,
                                 uint16_t* __restrict__ wq_hi, uint16_t* __restrict__ wq_lo,
                                 uint16_t* __restrict__ wo_hi, uint16_t* __restrict__ wo_lo)
{
    int i = blockIdx.x * blockDim.x + threadIdx.x;
    const float4* src;
    uint16_t *hi, *lo;
    int j;
    if (i < N4_X) {
        src = x;  hi = x_hi;  lo = x_lo;  j = i;
    } else if (i < N4_X + N4_WQ) {
        src = wq; hi = wq_hi; lo = wq_lo; j = i - N4_X;
    } else if (i < N4_X + N4_WQ + N4_WO) {
        src = wo; hi = wo_hi; lo = wo_lo; j = i - N4_X - N4_WQ;
    } else {
        return;
    }
    float4 v = src[j];
    uint32_t h0, l0, h1, l1;
    split_pair(make_float2(v.x, v.y), h0, l0);
    split_pair(make_float2(v.z, v.w), h1, l1);
    ((uint2*)hi)[j] = make_uint2(h0, h1);
    ((uint2*)lo)[j] = make_uint2(l0, l1);
}

// ===========================================================================
// GEMM v5 (QKV): block 128m x 192n, 8 warps (2m x 4n), warp 64x48,
// K-chunk 32, 2-stage cp.async, one sync per chunk. Split-plane output,
// Q columns (n < qcols) pre-scaled by 0.125. (unchanged from R12)
// ===========================================================================
#define H_OAH  0
#define H_OAL  10240
#define H_OBH  20480
#define H_OBL  33280
#define H_ST   46080
#define H_SMEM (2 * H_ST)   // 92160

__global__ __launch_bounds__(256)
void gemm_tc3(const uint16_t* __restrict__ Ah, const uint16_t* __restrict__ Al,
              const uint16_t* __restrict__ Bh, const uint16_t* __restrict__ Bl,
              const float* __restrict__ bias,
              uint16_t* __restrict__ Ch, uint16_t* __restrict__ Cl,
              int N, int K, int qcols)
{
    extern __shared__ char sm[];
    const uint32_t sbase = smem_u32(sm);

    const int tid  = threadIdx.x;
    const int lane = tid & 31;
    const int wid  = tid >> 5;
    const int wm   = wid & 1;
    const int wn   = wid >> 1;
    const int row0 = blockIdx.y * 128;
    const int col0 = blockIdx.x * 192;

    const int ar = tid >> 1;
    const uint16_t* Aph = Ah + (size_t)(row0 + ar) * K + (tid & 1) * 16;
    const uint16_t* Apl = Al + (size_t)(row0 + ar) * K + (tid & 1) * 16;
    const uint32_t sao = (uint32_t)(ar * 80 + (tid & 1) * 32);
    const int br = tid >> 3;
    const uint16_t* Bph = Bh + (size_t)br * N + col0 + (tid & 7) * 8;
    const uint16_t* Bpl = Bl + (size_t)br * N + col0 + (tid & 7) * 8;
    const uint32_t sbo = (uint32_t)(br * 400 + (tid & 7) * 16);

    const int g  = lane >> 3;
    const int rr = lane & 7;
    uint32_t abase[4];
    #pragma unroll
    for (int mt = 0; mt < 4; mt++)
        abase[mt] = (uint32_t)((wm * 64 + mt * 16 + (g & 1) * 8 + rr) * 40
                               + (g >> 1) * 8) * 2u;
    uint32_t bbase[3];
    #pragma unroll
    for (int p = 0; p < 3; p++)
        bbase[p] = (uint32_t)(((g & 1) * 8 + rr) * 200
                              + wn * 48 + p * 16 + (g >> 1) * 8) * 2u;

    float acc[4][6][4];
    #pragma unroll
    for (int i = 0; i < 4; i++)
        #pragma unroll
        for (int j = 0; j < 6; j++)
            #pragma unroll
            for (int r = 0; r < 4; r++)
                acc[i][j][r] = 0.f;

    auto LOAD = [&](int st, int k0) {
        uint32_t s0 = sbase + st * H_ST;
        cp16(s0 + H_OAH + sao,      Aph + k0);
        cp16(s0 + H_OAH + sao + 16, Aph + k0 + 8);
        cp16(s0 + H_OAL + sao,      Apl + k0);
        cp16(s0 + H_OAL + sao + 16, Apl + k0 + 8);
        const uint16_t* bh = Bph + (size_t)k0 * N;
        const uint16_t* bl = Bpl + (size_t)k0 * N;
        #pragma unroll
        for (int j = 0; j < 3; j++) {
            cp16(s0 + H_OBH + sbo + 128 * j, bh + 64 * j);
            cp16(s0 + H_OBL + sbo + 128 * j, bl + 64 * j);
        }
    };

    const int nk = K / 32;
    LOAD(0, 0);
    cp_commit();

    for (int kc = 0; kc < nk; kc++) {
        cp_wait<0>();
        __syncthreads();
        if (kc + 1 < nk) { LOAD((kc + 1) & 1, (kc + 1) * 32); cp_commit(); }

        uint32_t s0 = sbase + (kc & 1) * H_ST;
        #pragma unroll
        for (int ks = 0; ks < 2; ks++) {
            const uint32_t ka = ks * 32u;
            const uint32_t kb = ks * 6400u;
            uint32_t ahi[4][4], alo[4][4];
            #pragma unroll
            for (int mt = 0; mt < 4; mt++) {
                ldsm_x4(ahi[mt], s0 + H_OAH + abase[mt] + ka);
                ldsm_x4(alo[mt], s0 + H_OAL + abase[mt] + ka);
            }
            uint32_t bh[3][4], bl[3][4];
            #pragma unroll
            for (int p = 0; p < 3; p++) {
                ldsm_x4_t(bh[p], s0 + H_OBH + bbase[p] + kb);
                ldsm_x4_t(bl[p], s0 + H_OBL + bbase[p] + kb);
            }
            #pragma unroll
            for (int p = 0; p < 3; p++)
                #pragma unroll
                for (int mt = 0; mt < 4; mt++) {
                    mma_bf16(acc[mt][2 * p + 0], ahi[mt], bh[p]);
                    mma_bf16(acc[mt][2 * p + 1], ahi[mt], bh[p] + 2);
                }
            #pragma unroll
            for (int p = 0; p < 3; p++)
                #pragma unroll
                for (int mt = 0; mt < 4; mt++) {
                    mma_bf16(acc[mt][2 * p + 0], ahi[mt], bl[p]);
                    mma_bf16(acc[mt][2 * p + 1], ahi[mt], bl[p] + 2);
                }
            #pragma unroll
            for (int p = 0; p < 3; p++)
                #pragma unroll
                for (int mt = 0; mt < 4; mt++) {
                    mma_bf16(acc[mt][2 * p + 0], alo[mt], bh[p]);
                    mma_bf16(acc[mt][2 * p + 1], alo[mt], bh[p] + 2);
                }
        }
    }

    const int ml = lane >> 2;
    const int nl = 2 * (lane & 3);
    #pragma unroll
    for (int mt = 0; mt < 4; mt++) {
        #pragma unroll
        for (int nt = 0; nt < 6; nt++) {
            int m = row0 + wm * 64 + mt * 16 + ml;
            int n = col0 + wn * 48 + nt * 8 + nl;
            float2 bv = *(const float2*)&bias[n];
            float* c = acc[mt][nt];
            float sc = (n < qcols) ? 0.125f : 1.0f;
            float v0 = (c[0] + bv.x) * sc, v1 = (c[1] + bv.y) * sc;
            float w0 = (c[2] + bv.x) * sc, w1 = (c[3] + bv.y) * sc;
            uint32_t h, l;
            split_pair(make_float2(v0, v1), h, l);
            *(uint32_t*)(Ch + (size_t)m * N + n) = h;
            *(uint32_t*)(Cl + (size_t)m * N + n) = l;
            split_pair(make_float2(w0, w1), h, l);
            *(uint32_t*)(Ch + (size_t)(m + 8) * N + n) = h;
            *(uint32_t*)(Cl + (size_t)(m + 8) * N + n) = l;
        }
    }
}

// ===========================================================================
// GEMM v4 (out-proj, unchanged): 128x128, 2-stage, 2 CTAs/SM.
// ===========================================================================
#define G_OAH  0
#define G_OAL  10240
#define G_OBH  20480
#define G_OBL  29184
#define G_ST   37888
#define G_SMEM (2 * G_ST)

__global__ __launch_bounds__(256, 2)
void gemm_tc2(const uint16_t* __restrict__ Ah, const uint16_t* __restrict__ Al,
              const uint16_t* __restrict__ Bh, const uint16_t* __restrict__ Bl,
              const float* __restrict__ bias, float* __restrict__ Cf,
              int N, int K)
{
    extern __shared__ char sm[];
    const uint32_t sbase = smem_u32(sm);

    const int tid  = threadIdx.x;
    const int lane = tid & 31;
    const int wid  = tid >> 5;
    const int wm   = wid & 3;
    const int wn   = wid >> 2;
    const int row0 = blockIdx.y * 128;
    const int col0 = blockIdx.x * 128;

    const int ar  = tid >> 1;
    const int akc = (tid & 1) * 2;
    const int br  = tid >> 3;
    const int bnc = (tid & 7) * 2;

    const uint16_t* Aph = Ah + (size_t)(row0 + ar) * K + akc * 8;
    const uint16_t* Apl = Al + (size_t)(row0 + ar) * K + akc * 8;
    const uint16_t* Bph = Bh + (size_t)br * N + col0 + bnc * 8;
    const uint16_t* Bpl = Bl + (size_t)br * N + col0 + bnc * 8;

    const uint32_t sao0 = (uint32_t)(ar * 40 + akc * 8) * 2u;
    const uint32_t sao1 = sao0 + 16u;
    const uint32_t sbo0 = (uint32_t)(br * 136 + bnc * 8) * 2u;
    const uint32_t sbo1 = sbo0 + 16u;

    const int g  = lane >> 3;
    const int rr = lane & 7;
    uint32_t abase[2];
    #pragma unroll
    for (int mt = 0; mt < 2; mt++)
        abase[mt] = (uint32_t)((wm * 32 + mt * 16 + (g & 1) * 8 + rr) * 40
                               + (g >> 1) * 8) * 2u;
    uint32_t bbase[4];
    #pragma unroll
    for (int np = 0; np < 4; np++)
        bbase[np] = (uint32_t)(((g & 1) * 8 + rr) * 136
                               + wn * 64 + np * 16 + (g >> 1) * 8) * 2u;

    float acc[2][8][4];
    #pragma unroll
    for (int i = 0; i < 2; i++)
        #pragma unroll
        for (int j = 0; j < 8; j++)
            #pragma unroll
            for (int r = 0; r < 4; r++)
                acc[i][j][r] = 0.f;

    auto LOAD = [&](int st, int k0) {
        uint32_t s0 = sbase + st * G_ST;
        cp16(s0 + G_OAH + sao0, Aph + k0);
        cp16(s0 + G_OAH + sao1, Aph + k0 + 8);
        cp16(s0 + G_OAL + sao0, Apl + k0);
        cp16(s0 + G_OAL + sao1, Apl + k0 + 8);
        cp16(s0 + G_OBH + sbo0, Bph + (size_t)k0 * N);
        cp16(s0 + G_OBH + sbo1, Bph + (size_t)k0 * N + 8);
        cp16(s0 + G_OBL + sbo0, Bpl + (size_t)k0 * N);
        cp16(s0 + G_OBL + sbo1, Bpl + (size_t)k0 * N + 8);
    };

    const int nk = K / 32;
    LOAD(0, 0);  cp_commit();
    LOAD(1, 32); cp_commit();

    for (int kc = 0; kc < nk; kc++) {
        if (kc < nk - 1) cp_wait<1>();
        else             cp_wait<0>();
        __syncthreads();

        uint32_t s0 = sbase + (kc & 1) * G_ST;
        #pragma unroll
        for (int ks = 0; ks < 2; ks++) {
            const uint32_t ka = ks * 32u;
            const uint32_t kb = ks * 4352u;
            uint32_t ahi[2][4], alo[2][4];
            ldsm_x4(ahi[0], s0 + G_OAH + abase[0] + ka);
            ldsm_x4(ahi[1], s0 + G_OAH + abase[1] + ka);
            ldsm_x4(alo[0], s0 + G_OAL + abase[0] + ka);
            ldsm_x4(alo[1], s0 + G_OAL + abase[1] + ka);
            #pragma unroll
            for (int nph = 0; nph < 2; nph++) {
                uint32_t bh[2][4], bl[2][4];
                ldsm_x4_t(bh[0], s0 + G_OBH + bbase[2 * nph + 0] + kb);
                ldsm_x4_t(bl[0], s0 + G_OBL + bbase[2 * nph + 0] + kb);
                ldsm_x4_t(bh[1], s0 + G_OBH + bbase[2 * nph + 1] + kb);
                ldsm_x4_t(bl[1], s0 + G_OBL + bbase[2 * nph + 1] + kb);
                #pragma unroll
                for (int p = 0; p < 2; p++)
                    #pragma unroll
                    for (int mt = 0; mt < 2; mt++) {
                        mma_bf16(acc[mt][4 * nph + 2 * p + 0], ahi[mt], bh[p]);
                        mma_bf16(acc[mt][4 * nph + 2 * p + 1], ahi[mt], bh[p] + 2);
                    }
                #pragma unroll
                for (int p = 0; p < 2; p++)
                    #pragma unroll
                    for (int mt = 0; mt < 2; mt++) {
                        mma_bf16(acc[mt][4 * nph + 2 * p + 0], ahi[mt], bl[p]);
                        mma_bf16(acc[mt][4 * nph + 2 * p + 1], ahi[mt], bl[p] + 2);
                    }
                #pragma unroll
                for (int p = 0; p < 2; p++)
                    #pragma unroll
                    for (int mt = 0; mt < 2; mt++) {
                        mma_bf16(acc[mt][4 * nph + 2 * p + 0], alo[mt], bh[p]);
                        mma_bf16(acc[mt][4 * nph + 2 * p + 1], alo[mt], bh[p] + 2);
                    }
            }
        }
        __syncthreads();
        if (kc + 2 < nk) { LOAD(kc & 1, (kc + 2) * 32); cp_commit(); }
    }

    const int ml = lane >> 2;
    const int nl = 2 * (lane & 3);
    #pragma unroll
    for (int mt = 0; mt < 2; mt++) {
        #pragma unroll
        for (int nt = 0; nt < 8; nt++) {
            int m = row0 + wm * 32 + mt * 16 + ml;
            int n = col0 + wn * 64 + nt * 8 + nl;
            float2 bv = *(const float2*)&bias[n];
            float* c = acc[mt][nt];
            *(float2*)(Cf + (size_t)m * N + n) =
                make_float2(c[0] + bv.x, c[1] + bv.y);
            *(float2*)(Cf + (size_t)(m + 8) * N + n) =
                make_float2(c[2] + bv.x, c[3] + bv.y);
        }
    }
}

// ===========================================================================
// Flash attention (unchanged from R11): term-major + cp.async double buffer.
// ===========================================================================
#define FA_PAD  72
#define O_QHI   0
#define O_QLO   18432
#define KV_ST0  36864
#define P_KHI   0
#define P_KLO   9216
#define P_VHI   18432
#define P_VLO   27648
#define KV_STG  36864
#define FA_SMEM (KV_ST0 + 2 * KV_STG)   // 110592

__global__ __launch_bounds__(256)
void flash_attn_mma_kernel(const uint16_t* __restrict__ qkv_hi,
                           const uint16_t* __restrict__ qkv_lo,
                           uint16_t* __restrict__ attn_hi,
                           uint16_t* __restrict__ attn_lo)
{
    extern __shared__ char fsm[];
    const uint32_t sb = smem_u32(fsm);

    const int tid  = threadIdx.x;
    const int lane = tid & 31;
    const int wm   = tid >> 5;
    const int qt   = blockIdx.x;
    const int b    = blockIdx.y >> 4;
    const int h    = blockIdx.y & 15;

    {
        const int r  = tid >> 1;
        const int c0 = (tid & 1) * 32;
        const uint16_t* qh = qkv_hi + (size_t)(b * SEQ + qt * 128 + r) * QKVW
                                    + h * HD + c0;
        const uint16_t* ql = qkv_lo + (size_t)(b * SEQ + qt * 128 + r) * QKVW
                                    + h * HD + c0;
        uint32_t base = (uint32_t)(r * FA_PAD + c0) * 2u;
        #pragma unroll
        for (int s = 0; s < 4; s++) {
            *(uint4*)(fsm + O_QHI + base + 16 * s) = *(const uint4*)(qh + 8 * s);
            *(uint4*)(fsm + O_QLO + base + 16 * s) = *(const uint4*)(ql + 8 * s);
        }
    }

    const int kr  = tid >> 2;
    const int kc0 = (tid & 3) * 16;
    auto LOADKV = [&](int kt, int st) {
        size_t roff = (size_t)(b * SEQ + kt * 64 + kr) * QKVW + h * HD + kc0;
        const uint16_t* gh = qkv_hi + roff;
        const uint16_t* gl = qkv_lo + roff;
        uint32_t d = sb + KV_ST0 + (uint32_t)(st * KV_STG)
                   + (uint32_t)(kr * FA_PAD + kc0) * 2u;
        cp16(d + P_KHI,      gh + EMB);
        cp16(d + P_KHI + 16, gh + EMB + 8);
        cp16(d + P_KLO,      gl + EMB);
        cp16(d + P_KLO + 16, gl + EMB + 8);
        cp16(d + P_VHI,      gh + 2 * EMB);
        cp16(d + P_VHI + 16, gh + 2 * EMB + 8);
        cp16(d + P_VLO,      gl + 2 * EMB);
        cp16(d + P_VLO + 16, gl + 2 * EMB + 8);
    };

    LOADKV(0, 0);
    cp_commit();
    __syncthreads();

    const int g  = lane >> 3;
    const int rr = lane & 7;
    uint32_t qhi[4][4], qlo[4][4];
    {
        uint32_t moff = (uint32_t)((wm * 16 + (g & 1) * 8 + rr) * FA_PAD) * 2u;
        #pragma unroll
        for (int t = 0; t < 4; t++) {
            uint32_t koff = (uint32_t)((g >> 1) * 8 + 16 * t) * 2u;
            ldsm_x4(qhi[t], sb + O_QHI + moff + koff);
            ldsm_x4(qlo[t], sb + O_QLO + moff + koff);
        }
    }

    const uint32_t kbase = (uint32_t)(((g >> 1) * 8 + rr) * FA_PAD + (g & 1) * 8) * 2u;
    const uint32_t vbase = (uint32_t)(((g & 1) * 8 + rr) * FA_PAD + (g >> 1) * 8) * 2u;

    float m0 = -1e30f, m1 = -1e30f, l0 = 0.f, l1 = 0.f;
    float o[8][4];
    #pragma unroll
    for (int j = 0; j < 8; j++)
        #pragma unroll
        for (int r = 0; r < 4; r++) o[j][r] = 0.f;

    for (int kt = 0; kt < SEQ / 64; kt++) {
        cp_wait<0>();
        __syncthreads();
        if (kt + 1 < SEQ / 64) { LOADKV(kt + 1, (kt + 1) & 1); cp_commit(); }

        const uint32_t stg = sb + KV_ST0 + (uint32_t)((kt & 1) * KV_STG);

        float s[8][4];
        #pragma unroll
        for (int j = 0; j < 8; j++)
            #pragma unroll
            for (int r4 = 0; r4 < 4; r4++) s[j][r4] = 0.f;

        #pragma unroll
        for (int t = 0; t < 4; t++) {
            uint32_t kfh[4][4], kfl[4][4];
            #pragma unroll
            for (int nt = 0; nt < 4; nt++) {
                uint32_t off = kbase + (uint32_t)(nt * 16 * FA_PAD + 16 * t) * 2u;
                ldsm_x4(kfh[nt], stg + P_KHI + off);
                ldsm_x4(kfl[nt], stg + P_KLO + off);
            }
            #pragma unroll
            for (int nt = 0; nt < 4; nt++) {
                mma_bf16(s[2 * nt + 0], qhi[t], kfh[nt]);
                mma_bf16(s[2 * nt + 1], qhi[t], kfh[nt] + 2);
            }
            #pragma unroll
            for (int nt = 0; nt < 4; nt++) {
                mma_bf16(s[2 * nt + 0], qhi[t], kfl[nt]);
                mma_bf16(s[2 * nt + 1], qhi[t], kfl[nt] + 2);
            }
            #pragma unroll
            for (int nt = 0; nt < 4; nt++) {
                mma_bf16(s[2 * nt + 0], qlo[t], kfh[nt]);
                mma_bf16(s[2 * nt + 1], qlo[t], kfh[nt] + 2);
            }
        }

        float mx0 = -1e30f, mx1 = -1e30f;
        #pragma unroll
        for (int j = 0; j < 8; j++) {
            mx0 = fmaxf(mx0, fmaxf(s[j][0], s[j][1]));
            mx1 = fmaxf(mx1, fmaxf(s[j][2], s[j][3]));
        }
        mx0 = fmaxf(mx0, __shfl_xor_sync(0xffffffffu, mx0, 1));
        mx0 = fmaxf(mx0, __shfl_xor_sync(0xffffffffu, mx0, 2));
        mx1 = fmaxf(mx1, __shfl_xor_sync(0xffffffffu, mx1, 1));
        mx1 = fmaxf(mx1, __shfl_xor_sync(0xffffffffu, mx1, 2));

        float mn0 = fmaxf(m0, mx0), mn1 = fmaxf(m1, mx1);
        float a0 = __expf(m0 - mn0), a1 = __expf(m1 - mn1);
        m0 = mn0; m1 = mn1;

        float sum0 = 0.f, sum1 = 0.f;
        #pragma unroll
        for (int j = 0; j < 8; j++) {
            s[j][0] = __expf(s[j][0] - mn0);
            s[j][1] = __expf(s[j][1] - mn0);
            s[j][2] = __expf(s[j][2] - mn1);
            s[j][3] = __expf(s[j][3] - mn1);
            sum0 += s[j][0] + s[j][1];
            sum1 += s[j][2] + s[j][3];
        }
        sum0 += __shfl_xor_sync(0xffffffffu, sum0, 1);
        sum0 += __shfl_xor_sync(0xffffffffu, sum0, 2);
        sum1 += __shfl_xor_sync(0xffffffffu, sum1, 1);
        sum1 += __shfl_xor_sync(0xffffffffu, sum1, 2);
        l0 = l0 * a0 + sum0;
        l1 = l1 * a1 + sum1;

        #pragma unroll
        for (int j = 0; j < 8; j++) {
            o[j][0] *= a0; o[j][1] *= a0;
            o[j][2] *= a1; o[j][3] *= a1;
        }

        #pragma unroll
        for (int t = 0; t < 4; t++) {
            uint32_t phi[4], plo[4];
            split_pair(make_float2(s[2*t][0],   s[2*t][1]),   phi[0], plo[0]);
            split_pair(make_float2(s[2*t][2],   s[2*t][3]),   phi[1], plo[1]);
            split_pair(make_float2(s[2*t+1][0], s[2*t+1][1]), phi[2], plo[2]);
            split_pair(make_float2(s[2*t+1][2], s[2*t+1][3]), phi[3], plo[3]);
            uint32_t vfh[4][4], vfl[4][4];
            #pragma unroll
            for (int nt = 0; nt < 4; nt++) {
                uint32_t off = vbase + (uint32_t)(t * 16 * FA_PAD + nt * 16) * 2u;
                ldsm_x4_t(vfh[nt], stg + P_VHI + off);
                ldsm_x4_t(vfl[nt], stg + P_VLO + off);
            }
            #pragma unroll
            for (int nt = 0; nt < 4; nt++) {
                mma_bf16(o[2 * nt + 0], phi, vfh[nt]);
                mma_bf16(o[2 * nt + 1], phi, vfh[nt] + 2);
            }
            #pragma unroll
            for (int nt = 0; nt < 4; nt++) {
                mma_bf16(o[2 * nt + 0], phi, vfl[nt]);
                mma_bf16(o[2 * nt + 1], phi, vfl[nt] + 2);
            }
            #pragma unroll
            for (int nt = 0; nt < 4; nt++) {
                mma_bf16(o[2 * nt + 0], plo, vfh[nt]);
                mma_bf16(o[2 * nt + 1], plo, vfh[nt] + 2);
            }
        }
    }

    float inv0 = 1.f / l0, inv1 = 1.f / l1;
    int row = b * SEQ + qt * 128 + wm * 16 + (lane >> 2);
    size_t e0 = (size_t)row * EMB + h * HD + 2 * (lane & 3);
    #pragma unroll
    for (int j = 0; j < 8; j++) {
        uint32_t hh, ll;
        split_pair(make_float2(o[j][0] * inv0, o[j][1] * inv0), hh, ll);
        *(uint32_t*)(attn_hi + e0 + 8 * j) = hh;
        *(uint32_t*)(attn_lo + e0 + 8 * j) = ll;
        split_pair(make_float2(o[j][2] * inv1, o[j][3] * inv1), hh, ll);
        *(uint32_t*)(attn_hi + e0 + (size_t)8 * EMB + 8 * j) = hh;
        *(uint32_t*)(attn_lo + e0 + (size_t)8 * EMB + 8 * j) = ll;
    }
}

// ---------------------------------------------------------------------------
extern "C" void kernel_launch(void* const* d_in, const int* in_sizes, int n_in,
                              void* d_out, int out_size)
{
    (void)in_sizes; (void)n_in; (void)out_size;
    const float* x     = (const float*)d_in[0];
    const float* w_qkv = (const float*)d_in[1];
    const float* b_qkv = (const float*)d_in[2];
    const float* w_out = (const float*)d_in[3];
    const float* b_out = (const float*)d_in[4];
    float* out = (float*)d_out;

    uint16_t *x_hi, *x_lo, *wq_hi, *wq_lo, *wo_hi, *wo_lo;
    uint16_t *qkv_hi, *qkv_lo, *attn_hi, *attn_lo;
    cudaGetSymbolAddress((void**)&x_hi,   g_x_hi);
    cudaGetSymbolAddress((void**)&x_lo,   g_x_lo);
    cudaGetSymbolAddress((void**)&wq_hi,  g_wqkv_hi);
    cudaGetSymbolAddress((void**)&wq_lo,  g_wqkv_lo);
    cudaGetSymbolAddress((void**)&wo_hi,  g_wout_hi);
    cudaGetSymbolAddress((void**)&wo_lo,  g_wout_lo);
    cudaGetSymbolAddress((void**)&qkv_hi, g_qkv_hi);
    cudaGetSymbolAddress((void**)&qkv_lo, g_qkv_lo);
    cudaGetSymbolAddress((void**)&attn_hi, g_attn_hi);
    cudaGetSymbolAddress((void**)&attn_lo, g_attn_lo);

    cudaFuncSetAttribute(gemm_tc3,
                         cudaFuncAttributeMaxDynamicSharedMemorySize, H_SMEM);
    cudaFuncSetAttribute(gemm_tc2,
                         cudaFuncAttributeMaxDynamicSharedMemorySize, G_SMEM);
    cudaFuncSetAttribute(flash_attn_mma_kernel,
                         cudaFuncAttributeMaxDynamicSharedMemorySize, FA_SMEM);

    // 0) one merged split launch for x, W_qkv, W_out
    const int n4_total = N4_X + N4_WQ + N4_WO;   // 3145728
    split_all_kernel<<<(n4_total + 255) / 256, 256>>>(
        (const float4*)x, (const float4*)w_qkv, (const float4*)w_out,
        x_hi, x_lo, wq_hi, wq_lo, wo_hi, wo_lo);

    // 1) QKV projection (high-intensity tile) -> split planes
    gemm_tc3<<<dim3(QKVW / 192, NROWS / 128), 256, H_SMEM>>>(
        x_hi, x_lo, wq_hi, wq_lo, b_qkv, qkv_hi, qkv_lo, QKVW, EMB, EMB);

    // 2) attention -> split planes
    flash_attn_mma_kernel<<<dim3(SEQ / 128, BATCH * HEADS), 256, FA_SMEM>>>(
        qkv_hi, qkv_lo, attn_hi, attn_lo);

    // 3) output projection -> fp32 out
    gemm_tc2<<<dim3(EMB / 128, NROWS / 128), 256, G_SMEM>>>(
        attn_hi, attn_lo, wo_hi, wo_lo, b_out, out, EMB, EMB);
}

// round 14
// speedup vs baseline: 1.4265x; 1.4210x over previous
#include <cuda_runtime.h>
#include <cuda_fp16.h>
#include <cstdint>

#define EMB   1024
#define HEADS 16
#define HD    64
#define BATCH 4
#define SEQ   2048
#define NROWS (BATCH * SEQ)      // 8192
#define QKVW  (3 * EMB)          // 3072

// ---------------------------------------------------------------------------
// Global scratch: fp16 planes.
//  _hi = primary rn-f16 value; _lo = rn-f16 residual (A-side tensors only).
//  For K/V columns of qkv and for weights, only _hi is meaningful.
// ---------------------------------------------------------------------------
__device__ __align__(128) uint16_t g_x_hi[(size_t)NROWS * EMB];
__device__ __align__(128) uint16_t g_x_lo[(size_t)NROWS * EMB];
__device__ __align__(128) uint16_t g_wqkv[(size_t)EMB * QKVW];
__device__ __align__(128) uint16_t g_wout[(size_t)EMB * EMB];
__device__ __align__(128) uint16_t g_qkv_hi[(size_t)NROWS * QKVW];
__device__ __align__(128) uint16_t g_qkv_lo[(size_t)NROWS * QKVW];   // Q residual only
__device__ __align__(128) uint16_t g_attn_hi[(size_t)NROWS * EMB];
__device__ __align__(128) uint16_t g_attn_lo[(size_t)NROWS * EMB];

// ---------------------------------------------------------------------------
// Helpers
// ---------------------------------------------------------------------------
__device__ __forceinline__ uint32_t smem_u32(const void* p) {
    uint32_t a;
    asm("{ .reg .u64 t; cvta.to.shared.u64 t, %1; cvt.u32.u64 %0, t; }"
        : "=r"(a) : "l"(p));
    return a;
}
// 2-term fp16 split: hi = rn-f16(v), lo = rn-f16(v - hi). low16 = first elem.
__device__ __forceinline__ void split_f16(float2 v, uint32_t& hi, uint32_t& lo) {
    __half2 h = __floats2half2_rn(v.x, v.y);
    float2 hf = __half22float2(h);
    __half2 l = __floats2half2_rn(v.x - hf.x, v.y - hf.y);
    hi = *(uint32_t*)&h;
    lo = *(uint32_t*)&l;
}
__device__ __forceinline__ uint32_t pair_f16(float2 v) {
    __half2 h = __floats2half2_rn(v.x, v.y);
    return *(uint32_t*)&h;
}
__device__ __forceinline__ void ldsm_x4(uint32_t* r, uint32_t addr) {
    asm volatile("ldmatrix.sync.aligned.m8n8.x4.shared.b16 {%0,%1,%2,%3}, [%4];"
                 : "=r"(r[0]), "=r"(r[1]), "=r"(r[2]), "=r"(r[3]) : "r"(addr));
}
__device__ __forceinline__ void ldsm_x4_t(uint32_t* r, uint32_t addr) {
    asm volatile("ldmatrix.sync.aligned.m8n8.x4.trans.shared.b16 {%0,%1,%2,%3}, [%4];"
                 : "=r"(r[0]), "=r"(r[1]), "=r"(r[2]), "=r"(r[3]) : "r"(addr));
}
__device__ __forceinline__ void mma_f16(float* c, const uint32_t* a,
                                        const uint32_t* b) {
    asm volatile(
        "mma.sync.aligned.m16n8k16.row.col.f32.f16.f16.f32 "
        "{%0,%1,%2,%3}, {%4,%5,%6,%7}, {%8,%9}, {%0,%1,%2,%3};"
        : "+f"(c[0]), "+f"(c[1]), "+f"(c[2]), "+f"(c[3])
        : "r"(a[0]), "r"(a[1]), "r"(a[2]), "r"(a[3]), "r"(b[0]), "r"(b[1]));
}
__device__ __forceinline__ void cp16(uint32_t s, const void* g) {
    asm volatile("cp.async.cg.shared.global [%0], [%1], 16;" :: "r"(s), "l"(g));
}
__device__ __forceinline__ void cp_commit() {
    asm volatile("cp.async.commit_group;");
}
template<int N> __device__ __forceinline__ void cp_wait() {
    asm volatile("cp.async.wait_group %0;" :: "n"(N));
}

// ---------------------------------------------------------------------------
// Merged converts: x -> fp16 split planes; W_qkv, W_out -> single fp16.
// ---------------------------------------------------------------------------
#define N4_X  (NROWS * EMB / 4)
#define N4_WQ (EMB * QKVW / 4)
#define N4_WO (EMB * EMB / 4)

__global__ void split_all_kernel(const float4* __restrict__ x,
                                 const float4* __restrict__ wq,
                                 const float4* __restrict__ wo,
                                 uint16_t* __restrict__ x_hi, uint16_t* __restrict__ x_lo,
                                 uint16_t* __restrict__ wq_h, uint16_t* __restrict__ wo_h)
{
    int i = blockIdx.x * blockDim.x + threadIdx.x;
    if (i < N4_X) {
        float4 v = x[i];
        uint32_t h0, l0, h1, l1;
        split_f16(make_float2(v.x, v.y), h0, l0);
        split_f16(make_float2(v.z, v.w), h1, l1);
        ((uint2*)x_hi)[i] = make_uint2(h0, h1);
        ((uint2*)x_lo)[i] = make_uint2(l0, l1);
    } else if (i < N4_X + N4_WQ) {
        int j = i - N4_X;
        float4 v = wq[j];
        ((uint2*)wq_h)[j] = make_uint2(pair_f16(make_float2(v.x, v.y)),
                                       pair_f16(make_float2(v.z, v.w)));
    } else if (i < N4_X + N4_WQ + N4_WO) {
        int j = i - N4_X - N4_WQ;
        float4 v = wo[j];
        ((uint2*)wo_h)[j] = make_uint2(pair_f16(make_float2(v.x, v.y)),
                                       pair_f16(make_float2(v.z, v.w)));
    }
}

// ===========================================================================
// QKV GEMM: A = x (fp16 hi+lo), B = W_qkv (single fp16). 2-term MMA.
// Block 128m x 192n, 8 warps (2m x 4n), warp 64x48, K-chunk 32, 2-stage
// cp.async. Epilogue: Q cols (n<qcols) scaled 0.125 + 2-term split out;
// K/V cols single rn-f16 to Ch only.
// ===========================================================================
#define H_OAH  0
#define H_OAL  10240
#define H_OB   20480
#define H_ST   33280
#define H_SMEM (2 * H_ST)   // 66560

__global__ __launch_bounds__(256)
void gemm_qkv(const uint16_t* __restrict__ Ah, const uint16_t* __restrict__ Al,
              const uint16_t* __restrict__ Bh,
              const float* __restrict__ bias,
              uint16_t* __restrict__ Ch, uint16_t* __restrict__ Cl,
              int N, int K, int qcols)
{
    extern __shared__ char sm[];
    const uint32_t sbase = smem_u32(sm);

    const int tid  = threadIdx.x;
    const int lane = tid & 31;
    const int wid  = tid >> 5;
    const int wm   = wid & 1;
    const int wn   = wid >> 1;
    const int row0 = blockIdx.y * 128;
    const int col0 = blockIdx.x * 192;

    const int ar = tid >> 1;
    const uint16_t* Aph = Ah + (size_t)(row0 + ar) * K + (tid & 1) * 16;
    const uint16_t* Apl = Al + (size_t)(row0 + ar) * K + (tid & 1) * 16;
    const uint32_t sao = (uint32_t)(ar * 80 + (tid & 1) * 32);
    const int br = tid >> 3;
    const uint16_t* Bp = Bh + (size_t)br * N + col0 + (tid & 7) * 8;
    const uint32_t sbo = (uint32_t)(br * 400 + (tid & 7) * 16);

    const int g  = lane >> 3;
    const int rr = lane & 7;
    uint32_t abase[4];
    #pragma unroll
    for (int mt = 0; mt < 4; mt++)
        abase[mt] = (uint32_t)((wm * 64 + mt * 16 + (g & 1) * 8 + rr) * 40
                               + (g >> 1) * 8) * 2u;
    uint32_t bbase[3];
    #pragma unroll
    for (int p = 0; p < 3; p++)
        bbase[p] = (uint32_t)(((g & 1) * 8 + rr) * 200
                              + wn * 48 + p * 16 + (g >> 1) * 8) * 2u;

    float acc[4][6][4];
    #pragma unroll
    for (int i = 0; i < 4; i++)
        #pragma unroll
        for (int j = 0; j < 6; j++)
            #pragma unroll
            for (int r = 0; r < 4; r++)
                acc[i][j][r] = 0.f;

    auto LOAD = [&](int st, int k0) {
        uint32_t s0 = sbase + st * H_ST;
        cp16(s0 + H_OAH + sao,      Aph + k0);
        cp16(s0 + H_OAH + sao + 16, Aph + k0 + 8);
        cp16(s0 + H_OAL + sao,      Apl + k0);
        cp16(s0 + H_OAL + sao + 16, Apl + k0 + 8);
        const uint16_t* b = Bp + (size_t)k0 * N;
        #pragma unroll
        for (int j = 0; j < 3; j++)
            cp16(s0 + H_OB + sbo + 128 * j, b + 64 * j);
    };

    const int nk = K / 32;
    LOAD(0, 0);
    cp_commit();

    for (int kc = 0; kc < nk; kc++) {
        cp_wait<0>();
        __syncthreads();
        if (kc + 1 < nk) { LOAD((kc + 1) & 1, (kc + 1) * 32); cp_commit(); }

        uint32_t s0 = sbase + (kc & 1) * H_ST;
        #pragma unroll
        for (int ks = 0; ks < 2; ks++) {
            const uint32_t ka = ks * 32u;
            const uint32_t kb = ks * 6400u;
            uint32_t ahi[4][4], alo[4][4];
            #pragma unroll
            for (int mt = 0; mt < 4; mt++) {
                ldsm_x4(ahi[mt], s0 + H_OAH + abase[mt] + ka);
                ldsm_x4(alo[mt], s0 + H_OAL + abase[mt] + ka);
            }
            uint32_t bf[3][4];
            #pragma unroll
            for (int p = 0; p < 3; p++)
                ldsm_x4_t(bf[p], s0 + H_OB + bbase[p] + kb);
            // term 1: Ahi * B (24 distinct accumulators)
            #pragma unroll
            for (int p = 0; p < 3; p++)
                #pragma unroll
                for (int mt = 0; mt < 4; mt++) {
                    mma_f16(acc[mt][2 * p + 0], ahi[mt], bf[p]);
                    mma_f16(acc[mt][2 * p + 1], ahi[mt], bf[p] + 2);
                }
            // term 2: Alo * B
            #pragma unroll
            for (int p = 0; p < 3; p++)
                #pragma unroll
                for (int mt = 0; mt < 4; mt++) {
                    mma_f16(acc[mt][2 * p + 0], alo[mt], bf[p]);
                    mma_f16(acc[mt][2 * p + 1], alo[mt], bf[p] + 2);
                }
        }
    }

    const int ml = lane >> 2;
    const int nl = 2 * (lane & 3);
    #pragma unroll
    for (int mt = 0; mt < 4; mt++) {
        #pragma unroll
        for (int nt = 0; nt < 6; nt++) {
            int m = row0 + wm * 64 + mt * 16 + ml;
            int n = col0 + wn * 48 + nt * 8 + nl;
            float2 bv = *(const float2*)&bias[n];
            float* c = acc[mt][nt];
            if (n < qcols) {
                // Q: scale and 2-term split
                float v0 = (c[0] + bv.x) * 0.125f, v1 = (c[1] + bv.y) * 0.125f;
                float w0 = (c[2] + bv.x) * 0.125f, w1 = (c[3] + bv.y) * 0.125f;
                uint32_t h, l;
                split_f16(make_float2(v0, v1), h, l);
                *(uint32_t*)(Ch + (size_t)m * N + n) = h;
                *(uint32_t*)(Cl + (size_t)m * N + n) = l;
                split_f16(make_float2(w0, w1), h, l);
                *(uint32_t*)(Ch + (size_t)(m + 8) * N + n) = h;
                *(uint32_t*)(Cl + (size_t)(m + 8) * N + n) = l;
            } else {
                // K/V: single rn-f16
                *(uint32_t*)(Ch + (size_t)m * N + n) =
                    pair_f16(make_float2(c[0] + bv.x, c[1] + bv.y));
                *(uint32_t*)(Ch + (size_t)(m + 8) * N + n) =
                    pair_f16(make_float2(c[2] + bv.x, c[3] + bv.y));
            }
        }
    }
}

// ===========================================================================
// Out-proj GEMM: A = attn (fp16 hi+lo), B = W_out (single fp16). 2-term MMA.
// 128x128 tile, 8 warps (4m x 2n), K-chunk 32, 2-stage cp.async, 2 CTAs/SM.
// ===========================================================================
#define G_OAH  0
#define G_OAL  10240
#define G_OB   20480
#define G_ST   29184
#define G_SMEM (2 * G_ST)   // 58368

__global__ __launch_bounds__(256, 2)
void gemm_out(const uint16_t* __restrict__ Ah, const uint16_t* __restrict__ Al,
              const uint16_t* __restrict__ Bh,
              const float* __restrict__ bias, float* __restrict__ Cf,
              int N, int K)
{
    extern __shared__ char sm[];
    const uint32_t sbase = smem_u32(sm);

    const int tid  = threadIdx.x;
    const int lane = tid & 31;
    const int wid  = tid >> 5;
    const int wm   = wid & 3;
    const int wn   = wid >> 2;
    const int row0 = blockIdx.y * 128;
    const int col0 = blockIdx.x * 128;

    const int ar  = tid >> 1;
    const int akc = (tid & 1) * 2;
    const int br  = tid >> 3;
    const int bnc = (tid & 7) * 2;

    const uint16_t* Aph = Ah + (size_t)(row0 + ar) * K + akc * 8;
    const uint16_t* Apl = Al + (size_t)(row0 + ar) * K + akc * 8;
    const uint16_t* Bp  = Bh + (size_t)br * N + col0 + bnc * 8;

    const uint32_t sao0 = (uint32_t)(ar * 40 + akc * 8) * 2u;
    const uint32_t sao1 = sao0 + 16u;
    const uint32_t sbo0 = (uint32_t)(br * 136 + bnc * 8) * 2u;
    const uint32_t sbo1 = sbo0 + 16u;

    const int g  = lane >> 3;
    const int rr = lane & 7;
    uint32_t abase[2];
    #pragma unroll
    for (int mt = 0; mt < 2; mt++)
        abase[mt] = (uint32_t)((wm * 32 + mt * 16 + (g & 1) * 8 + rr) * 40
                               + (g >> 1) * 8) * 2u;
    uint32_t bbase[4];
    #pragma unroll
    for (int np = 0; np < 4; np++)
        bbase[np] = (uint32_t)(((g & 1) * 8 + rr) * 136
                               + wn * 64 + np * 16 + (g >> 1) * 8) * 2u;

    float acc[2][8][4];
    #pragma unroll
    for (int i = 0; i < 2; i++)
        #pragma unroll
        for (int j = 0; j < 8; j++)
            #pragma unroll
            for (int r = 0; r < 4; r++)
                acc[i][j][r] = 0.f;

    auto LOAD = [&](int st, int k0) {
        uint32_t s0 = sbase + st * G_ST;
        cp16(s0 + G_OAH + sao0, Aph + k0);
        cp16(s0 + G_OAH + sao1, Aph + k0 + 8);
        cp16(s0 + G_OAL + sao0, Apl + k0);
        cp16(s0 + G_OAL + sao1, Apl + k0 + 8);
        cp16(s0 + G_OB + sbo0, Bp + (size_t)k0 * N);
        cp16(s0 + G_OB + sbo1, Bp + (size_t)k0 * N + 8);
    };

    const int nk = K / 32;
    LOAD(0, 0);
    cp_commit();

    for (int kc = 0; kc < nk; kc++) {
        cp_wait<0>();
        __syncthreads();
        if (kc + 1 < nk) { LOAD((kc + 1) & 1, (kc + 1) * 32); cp_commit(); }

        uint32_t s0 = sbase + (kc & 1) * G_ST;
        #pragma unroll
        for (int ks = 0; ks < 2; ks++) {
            const uint32_t ka = ks * 32u;
            const uint32_t kb = ks * 4352u;
            uint32_t ahi[2][4], alo[2][4];
            ldsm_x4(ahi[0], s0 + G_OAH + abase[0] + ka);
            ldsm_x4(ahi[1], s0 + G_OAH + abase[1] + ka);
            ldsm_x4(alo[0], s0 + G_OAL + abase[0] + ka);
            ldsm_x4(alo[1], s0 + G_OAL + abase[1] + ka);
            uint32_t bf[4][4];
            #pragma unroll
            for (int np = 0; np < 4; np++)
                ldsm_x4_t(bf[np], s0 + G_OB + bbase[np] + kb);
            // term 1: Ahi * B (16 distinct accumulators)
            #pragma unroll
            for (int np = 0; np < 4; np++)
                #pragma unroll
                for (int mt = 0; mt < 2; mt++) {
                    mma_f16(acc[mt][2 * np + 0], ahi[mt], bf[np]);
                    mma_f16(acc[mt][2 * np + 1], ahi[mt], bf[np] + 2);
                }
            // term 2: Alo * B
            #pragma unroll
            for (int np = 0; np < 4; np++)
                #pragma unroll
                for (int mt = 0; mt < 2; mt++) {
                    mma_f16(acc[mt][2 * np + 0], alo[mt], bf[np]);
                    mma_f16(acc[mt][2 * np + 1], alo[mt], bf[np] + 2);
                }
        }
    }

    const int ml = lane >> 2;
    const int nl = 2 * (lane & 3);
    #pragma unroll
    for (int mt = 0; mt < 2; mt++) {
        #pragma unroll
        for (int nt = 0; nt < 8; nt++) {
            int m = row0 + wm * 32 + mt * 16 + ml;
            int n = col0 + wn * 64 + nt * 8 + nl;
            float2 bv = *(const float2*)&bias[n];
            float* c = acc[mt][nt];
            *(float2*)(Cf + (size_t)m * N + n) =
                make_float2(c[0] + bv.x, c[1] + bv.y);
            *(float2*)(Cf + (size_t)(m + 8) * N + n) =
                make_float2(c[2] + bv.x, c[3] + bv.y);
        }
    }
}

// ===========================================================================
// Flash attention: Q 2-term fp16 (in regs), K/V single fp16 (cp.async
// double-buffered), P 2-term fp16 split in-register. Term-major ordering.
// Block = 128 q-rows x (b,h); 256 threads. smem 73728 -> up to 2 CTAs/SM.
// ===========================================================================
#define FA_PAD  72
#define O_QHI   0
#define O_QLO   18432
#define KV_ST0  36864
#define P_K     0
#define P_V     9216
#define KV_STG  18432
#define FA_SMEM (KV_ST0 + 2 * KV_STG)   // 73728

__global__ __launch_bounds__(256)
void flash_attn_mma_kernel(const uint16_t* __restrict__ qkv_hi,
                           const uint16_t* __restrict__ qkv_lo,
                           uint16_t* __restrict__ attn_hi,
                           uint16_t* __restrict__ attn_lo)
{
    extern __shared__ char fsm[];
    const uint32_t sb = smem_u32(fsm);

    const int tid  = threadIdx.x;
    const int lane = tid & 31;
    const int wm   = tid >> 5;
    const int qt   = blockIdx.x;
    const int b    = blockIdx.y >> 4;
    const int h    = blockIdx.y & 15;

    // ---- load Q tile (hi+lo fp16, pre-scaled upstream) ----
    {
        const int r  = tid >> 1;
        const int c0 = (tid & 1) * 32;
        const uint16_t* qh = qkv_hi + (size_t)(b * SEQ + qt * 128 + r) * QKVW
                                    + h * HD + c0;
        const uint16_t* ql = qkv_lo + (size_t)(b * SEQ + qt * 128 + r) * QKVW
                                    + h * HD + c0;
        uint32_t base = (uint32_t)(r * FA_PAD + c0) * 2u;
        #pragma unroll
        for (int s = 0; s < 4; s++) {
            *(uint4*)(fsm + O_QHI + base + 16 * s) = *(const uint4*)(qh + 8 * s);
            *(uint4*)(fsm + O_QLO + base + 16 * s) = *(const uint4*)(ql + 8 * s);
        }
    }

    // K/V single-plane cp.async loader
    const int kr  = tid >> 2;
    const int kc0 = (tid & 3) * 16;
    auto LOADKV = [&](int kt, int st) {
        size_t roff = (size_t)(b * SEQ + kt * 64 + kr) * QKVW + h * HD + kc0;
        const uint16_t* gk = qkv_hi + roff + EMB;
        const uint16_t* gv = qkv_hi + roff + 2 * EMB;
        uint32_t d = sb + KV_ST0 + (uint32_t)(st * KV_STG)
                   + (uint32_t)(kr * FA_PAD + kc0) * 2u;
        cp16(d + P_K,      gk);
        cp16(d + P_K + 16, gk + 8);
        cp16(d + P_V,      gv);
        cp16(d + P_V + 16, gv + 8);
    };

    LOADKV(0, 0);
    cp_commit();
    __syncthreads();

    // ---- preload Q fragments ----
    const int g  = lane >> 3;
    const int rr = lane & 7;
    uint32_t qhi[4][4], qlo[4][4];
    {
        uint32_t moff = (uint32_t)((wm * 16 + (g & 1) * 8 + rr) * FA_PAD) * 2u;
        #pragma unroll
        for (int t = 0; t < 4; t++) {
            uint32_t koff = (uint32_t)((g >> 1) * 8 + 16 * t) * 2u;
            ldsm_x4(qhi[t], sb + O_QHI + moff + koff);
            ldsm_x4(qlo[t], sb + O_QLO + moff + koff);
        }
    }

    const uint32_t kbase = (uint32_t)(((g >> 1) * 8 + rr) * FA_PAD + (g & 1) * 8) * 2u;
    const uint32_t vbase = (uint32_t)(((g & 1) * 8 + rr) * FA_PAD + (g >> 1) * 8) * 2u;

    float m0 = -1e30f, m1 = -1e30f, l0 = 0.f, l1 = 0.f;
    float o[8][4];
    #pragma unroll
    for (int j = 0; j < 8; j++)
        #pragma unroll
        for (int r = 0; r < 4; r++) o[j][r] = 0.f;

    for (int kt = 0; kt < SEQ / 64; kt++) {
        cp_wait<0>();
        __syncthreads();
        if (kt + 1 < SEQ / 64) { LOADKV(kt + 1, (kt + 1) & 1); cp_commit(); }

        const uint32_t stg = sb + KV_ST0 + (uint32_t)((kt & 1) * KV_STG);

        // ---- S = (Qhi + Qlo) K^T : 2-term, term-major ----
        float s[8][4];
        #pragma unroll
        for (int j = 0; j < 8; j++)
            #pragma unroll
            for (int r4 = 0; r4 < 4; r4++) s[j][r4] = 0.f;

        #pragma unroll
        for (int t = 0; t < 4; t++) {
            uint32_t kf[4][4];
            #pragma unroll
            for (int nt = 0; nt < 4; nt++) {
                uint32_t off = kbase + (uint32_t)(nt * 16 * FA_PAD + 16 * t) * 2u;
                ldsm_x4(kf[nt], stg + P_K + off);
            }
            #pragma unroll
            for (int nt = 0; nt < 4; nt++) {
                mma_f16(s[2 * nt + 0], qhi[t], kf[nt]);
                mma_f16(s[2 * nt + 1], qhi[t], kf[nt] + 2);
            }
            #pragma unroll
            for (int nt = 0; nt < 4; nt++) {
                mma_f16(s[2 * nt + 0], qlo[t], kf[nt]);
                mma_f16(s[2 * nt + 1], qlo[t], kf[nt] + 2);
            }
        }

        // ---- online softmax ----
        float mx0 = -1e30f, mx1 = -1e30f;
        #pragma unroll
        for (int j = 0; j < 8; j++) {
            mx0 = fmaxf(mx0, fmaxf(s[j][0], s[j][1]));
            mx1 = fmaxf(mx1, fmaxf(s[j][2], s[j][3]));
        }
        mx0 = fmaxf(mx0, __shfl_xor_sync(0xffffffffu, mx0, 1));
        mx0 = fmaxf(mx0, __shfl_xor_sync(0xffffffffu, mx0, 2));
        mx1 = fmaxf(mx1, __shfl_xor_sync(0xffffffffu, mx1, 1));
        mx1 = fmaxf(mx1, __shfl_xor_sync(0xffffffffu, mx1, 2));

        float mn0 = fmaxf(m0, mx0), mn1 = fmaxf(m1, mx1);
        float a0 = __expf(m0 - mn0), a1 = __expf(m1 - mn1);
        m0 = mn0; m1 = mn1;

        float sum0 = 0.f, sum1 = 0.f;
        #pragma unroll
        for (int j = 0; j < 8; j++) {
            s[j][0] = __expf(s[j][0] - mn0);
            s[j][1] = __expf(s[j][1] - mn0);
            s[j][2] = __expf(s[j][2] - mn1);
            s[j][3] = __expf(s[j][3] - mn1);
            sum0 += s[j][0] + s[j][1];
            sum1 += s[j][2] + s[j][3];
        }
        sum0 += __shfl_xor_sync(0xffffffffu, sum0, 1);
        sum0 += __shfl_xor_sync(0xffffffffu, sum0, 2);
        sum1 += __shfl_xor_sync(0xffffffffu, sum1, 1);
        sum1 += __shfl_xor_sync(0xffffffffu, sum1, 2);
        l0 = l0 * a0 + sum0;
        l1 = l1 * a1 + sum1;

        #pragma unroll
        for (int j = 0; j < 8; j++) {
            o[j][0] *= a0; o[j][1] *= a0;
            o[j][2] *= a1; o[j][3] *= a1;
        }

        // ---- o += (Phi + Plo) V : 2-term, term-major ----
        #pragma unroll
        for (int t = 0; t < 4; t++) {
            uint32_t phi[4], plo[4];
            split_f16(make_float2(s[2*t][0],   s[2*t][1]),   phi[0], plo[0]);
            split_f16(make_float2(s[2*t][2],   s[2*t][3]),   phi[1], plo[1]);
            split_f16(make_float2(s[2*t+1][0], s[2*t+1][1]), phi[2], plo[2]);
            split_f16(make_float2(s[2*t+1][2], s[2*t+1][3]), phi[3], plo[3]);
            uint32_t vf[4][4];
            #pragma unroll
            for (int nt = 0; nt < 4; nt++) {
                uint32_t off = vbase + (uint32_t)(t * 16 * FA_PAD + nt * 16) * 2u;
                ldsm_x4_t(vf[nt], stg + P_V + off);
            }
            #pragma unroll
            for (int nt = 0; nt < 4; nt++) {
                mma_f16(o[2 * nt + 0], phi, vf[nt]);
                mma_f16(o[2 * nt + 1], phi, vf[nt] + 2);
            }
            #pragma unroll
            for (int nt = 0; nt < 4; nt++) {
                mma_f16(o[2 * nt + 0], plo, vf[nt]);
                mma_f16(o[2 * nt + 1], plo, vf[nt] + 2);
            }
        }
    }

    // ---- epilogue: normalize, 2-term split, write planes ----
    float inv0 = 1.f / l0, inv1 = 1.f / l1;
    int row = b * SEQ + qt * 128 + wm * 16 + (lane >> 2);
    size_t e0 = (size_t)row * EMB + h * HD + 2 * (lane & 3);
    #pragma unroll
    for (int j = 0; j < 8; j++) {
        uint32_t hh, ll;
        split_f16(make_float2(o[j][0] * inv0, o[j][1] * inv0), hh, ll);
        *(uint32_t*)(attn_hi + e0 + 8 * j) = hh;
        *(uint32_t*)(attn_lo + e0 + 8 * j) = ll;
        split_f16(make_float2(o[j][2] * inv1, o[j][3] * inv1), hh, ll);
        *(uint32_t*)(attn_hi + e0 + (size_t)8 * EMB + 8 * j) = hh;
        *(uint32_t*)(attn_lo + e0 + (size_t)8 * EMB + 8 * j) = ll;
    }
}

// ---------------------------------------------------------------------------
extern "C" void kernel_launch(void* const* d_in, const int* in_sizes, int n_in,
                              void* d_out, int out_size)
{
    (void)in_sizes; (void)n_in; (void)out_size;
    const float* x     = (const float*)d_in[0];
    const float* w_qkv = (const float*)d_in[1];
    const float* b_qkv = (const float*)d_in[2];
    const float* w_out = (const float*)d_in[3];
    const float* b_out = (const float*)d_in[4];
    float* out = (float*)d_out;

    uint16_t *x_hi, *x_lo, *wq, *wo, *qkv_hi, *qkv_lo, *attn_hi, *attn_lo;
    cudaGetSymbolAddress((void**)&x_hi,   g_x_hi);
    cudaGetSymbolAddress((void**)&x_lo,   g_x_lo);
    cudaGetSymbolAddress((void**)&wq,     g_wqkv);
    cudaGetSymbolAddress((void**)&wo,     g_wout);
    cudaGetSymbolAddress((void**)&qkv_hi, g_qkv_hi);
    cudaGetSymbolAddress((void**)&qkv_lo, g_qkv_lo);
    cudaGetSymbolAddress((void**)&attn_hi, g_attn_hi);
    cudaGetSymbolAddress((void**)&attn_lo, g_attn_lo);

    cudaFuncSetAttribute(gemm_qkv,
                         cudaFuncAttributeMaxDynamicSharedMemorySize, H_SMEM);
    cudaFuncSetAttribute(gemm_out,
                         cudaFuncAttributeMaxDynamicSharedMemorySize, G_SMEM);
    cudaFuncSetAttribute(flash_attn_mma_kernel,
                         cudaFuncAttributeMaxDynamicSharedMemorySize, FA_SMEM);

    // 0) merged converts
    const int n4_total = N4_X + N4_WQ + N4_WO;
    split_all_kernel<<<(n4_total + 255) / 256, 256>>>(
        (const float4*)x, (const float4*)w_qkv, (const float4*)w_out,
        x_hi, x_lo, wq, wo);

    // 1) QKV projection (2-term fp16) -> Q split planes, K/V single plane
    gemm_qkv<<<dim3(QKVW / 192, NROWS / 128), 256, H_SMEM>>>(
        x_hi, x_lo, wq, b_qkv, qkv_hi, qkv_lo, QKVW, EMB, EMB);

    // 2) attention (2-term fp16) -> split planes
    flash_attn_mma_kernel<<<dim3(SEQ / 128, BATCH * HEADS), 256, FA_SMEM>>>(
        qkv_hi, qkv_lo, attn_hi, attn_lo);

    // 3) output projection (2-term fp16) -> fp32 out
    gemm_out<<<dim3(EMB / 128, NROWS / 128), 256, G_SMEM>>>(
        attn_hi, attn_lo, wo, b_out, out, EMB, EMB);
}

// round 15
// speedup vs baseline: 1.6557x; 1.1607x over previous
#include <cuda_runtime.h>
#include <cuda_fp16.h>
#include <cstdint>

#define EMB   1024
#define HEADS 16
#define HD    64
#define BATCH 4
#define SEQ   2048
#define NROWS (BATCH * SEQ)      // 8192
#define QKVW  (3 * EMB)          // 3072

// ---------------------------------------------------------------------------
// Global scratch: fp16 planes.
// ---------------------------------------------------------------------------
__device__ __align__(128) uint16_t g_x_hi[(size_t)NROWS * EMB];
__device__ __align__(128) uint16_t g_x_lo[(size_t)NROWS * EMB];
__device__ __align__(128) uint16_t g_wqkv[(size_t)EMB * QKVW];
__device__ __align__(128) uint16_t g_wout[(size_t)EMB * EMB];
__device__ __align__(128) uint16_t g_qkv_hi[(size_t)NROWS * QKVW];
__device__ __align__(128) uint16_t g_qkv_lo[(size_t)NROWS * QKVW];   // Q residual only
__device__ __align__(128) uint16_t g_attn_hi[(size_t)NROWS * EMB];
__device__ __align__(128) uint16_t g_attn_lo[(size_t)NROWS * EMB];

// ---------------------------------------------------------------------------
// Helpers
// ---------------------------------------------------------------------------
__device__ __forceinline__ uint32_t smem_u32(const void* p) {
    uint32_t a;
    asm("{ .reg .u64 t; cvta.to.shared.u64 t, %1; cvt.u32.u64 %0, t; }"
        : "=r"(a) : "l"(p));
    return a;
}
__device__ __forceinline__ void split_f16(float2 v, uint32_t& hi, uint32_t& lo) {
    __half2 h = __floats2half2_rn(v.x, v.y);
    float2 hf = __half22float2(h);
    __half2 l = __floats2half2_rn(v.x - hf.x, v.y - hf.y);
    hi = *(uint32_t*)&h;
    lo = *(uint32_t*)&l;
}
__device__ __forceinline__ uint32_t pair_f16(float2 v) {
    __half2 h = __floats2half2_rn(v.x, v.y);
    return *(uint32_t*)&h;
}
__device__ __forceinline__ void ldsm_x4(uint32_t* r, uint32_t addr) {
    asm volatile("ldmatrix.sync.aligned.m8n8.x4.shared.b16 {%0,%1,%2,%3}, [%4];"
                 : "=r"(r[0]), "=r"(r[1]), "=r"(r[2]), "=r"(r[3]) : "r"(addr));
}
__device__ __forceinline__ void ldsm_x4_t(uint32_t* r, uint32_t addr) {
    asm volatile("ldmatrix.sync.aligned.m8n8.x4.trans.shared.b16 {%0,%1,%2,%3}, [%4];"
                 : "=r"(r[0]), "=r"(r[1]), "=r"(r[2]), "=r"(r[3]) : "r"(addr));
}
__device__ __forceinline__ void mma_f16(float* c, const uint32_t* a,
                                        const uint32_t* b) {
    asm volatile(
        "mma.sync.aligned.m16n8k16.row.col.f32.f16.f16.f32 "
        "{%0,%1,%2,%3}, {%4,%5,%6,%7}, {%8,%9}, {%0,%1,%2,%3};"
        : "+f"(c[0]), "+f"(c[1]), "+f"(c[2]), "+f"(c[3])
        : "r"(a[0]), "r"(a[1]), "r"(a[2]), "r"(a[3]), "r"(b[0]), "r"(b[1]));
}
__device__ __forceinline__ void cp16(uint32_t s, const void* g) {
    asm volatile("cp.async.cg.shared.global [%0], [%1], 16;" :: "r"(s), "l"(g));
}
__device__ __forceinline__ void cp_commit() {
    asm volatile("cp.async.commit_group;");
}
template<int N> __device__ __forceinline__ void cp_wait() {
    asm volatile("cp.async.wait_group %0;" :: "n"(N));
}

// ---------------------------------------------------------------------------
// Merged converts: x -> fp16 split planes; W_qkv, W_out -> single fp16.
// ---------------------------------------------------------------------------
#define N4_X  (NROWS * EMB / 4)
#define N4_WQ (EMB * QKVW / 4)
#define N4_WO (EMB * EMB / 4)

__global__ void split_all_kernel(const float4* __restrict__ x,
                                 const float4* __restrict__ wq,
                                 const float4* __restrict__ wo,
                                 uint16_t* __restrict__ x_hi, uint16_t* __restrict__ x_lo,
                                 uint16_t* __restrict__ wq_h, uint16_t* __restrict__ wo_h)
{
    int i = blockIdx.x * blockDim.x + threadIdx.x;
    if (i < N4_X) {
        float4 v = x[i];
        uint32_t h0, l0, h1, l1;
        split_f16(make_float2(v.x, v.y), h0, l0);
        split_f16(make_float2(v.z, v.w), h1, l1);
        ((uint2*)x_hi)[i] = make_uint2(h0, h1);
        ((uint2*)x_lo)[i] = make_uint2(l0, l1);
    } else if (i < N4_X + N4_WQ) {
        int j = i - N4_X;
        float4 v = wq[j];
        ((uint2*)wq_h)[j] = make_uint2(pair_f16(make_float2(v.x, v.y)),
                                       pair_f16(make_float2(v.z, v.w)));
    } else if (i < N4_X + N4_WQ + N4_WO) {
        int j = i - N4_X - N4_WQ;
        float4 v = wo[j];
        ((uint2*)wo_h)[j] = make_uint2(pair_f16(make_float2(v.x, v.y)),
                                       pair_f16(make_float2(v.z, v.w)));
    }
}

// ===========================================================================
// QKV GEMM (unchanged from R14): A = x (hi+lo), B = W_qkv (single). 2-term.
// ===========================================================================
#define H_OAH  0
#define H_OAL  10240
#define H_OB   20480
#define H_ST   33280
#define H_SMEM (2 * H_ST)   // 66560

__global__ __launch_bounds__(256)
void gemm_qkv(const uint16_t* __restrict__ Ah, const uint16_t* __restrict__ Al,
              const uint16_t* __restrict__ Bh,
              const float* __restrict__ bias,
              uint16_t* __restrict__ Ch, uint16_t* __restrict__ Cl,
              int N, int K, int qcols)
{
    extern __shared__ char sm[];
    const uint32_t sbase = smem_u32(sm);

    const int tid  = threadIdx.x;
    const int lane = tid & 31;
    const int wid  = tid >> 5;
    const int wm   = wid & 1;
    const int wn   = wid >> 1;
    const int row0 = blockIdx.y * 128;
    const int col0 = blockIdx.x * 192;

    const int ar = tid >> 1;
    const uint16_t* Aph = Ah + (size_t)(row0 + ar) * K + (tid & 1) * 16;
    const uint16_t* Apl = Al + (size_t)(row0 + ar) * K + (tid & 1) * 16;
    const uint32_t sao = (uint32_t)(ar * 80 + (tid & 1) * 32);
    const int br = tid >> 3;
    const uint16_t* Bp = Bh + (size_t)br * N + col0 + (tid & 7) * 8;
    const uint32_t sbo = (uint32_t)(br * 400 + (tid & 7) * 16);

    const int g  = lane >> 3;
    const int rr = lane & 7;
    uint32_t abase[4];
    #pragma unroll
    for (int mt = 0; mt < 4; mt++)
        abase[mt] = (uint32_t)((wm * 64 + mt * 16 + (g & 1) * 8 + rr) * 40
                               + (g >> 1) * 8) * 2u;
    uint32_t bbase[3];
    #pragma unroll
    for (int p = 0; p < 3; p++)
        bbase[p] = (uint32_t)(((g & 1) * 8 + rr) * 200
                              + wn * 48 + p * 16 + (g >> 1) * 8) * 2u;

    float acc[4][6][4];
    #pragma unroll
    for (int i = 0; i < 4; i++)
        #pragma unroll
        for (int j = 0; j < 6; j++)
            #pragma unroll
            for (int r = 0; r < 4; r++)
                acc[i][j][r] = 0.f;

    auto LOAD = [&](int st, int k0) {
        uint32_t s0 = sbase + st * H_ST;
        cp16(s0 + H_OAH + sao,      Aph + k0);
        cp16(s0 + H_OAH + sao + 16, Aph + k0 + 8);
        cp16(s0 + H_OAL + sao,      Apl + k0);
        cp16(s0 + H_OAL + sao + 16, Apl + k0 + 8);
        const uint16_t* b = Bp + (size_t)k0 * N;
        #pragma unroll
        for (int j = 0; j < 3; j++)
            cp16(s0 + H_OB + sbo + 128 * j, b + 64 * j);
    };

    const int nk = K / 32;
    LOAD(0, 0);
    cp_commit();

    for (int kc = 0; kc < nk; kc++) {
        cp_wait<0>();
        __syncthreads();
        if (kc + 1 < nk) { LOAD((kc + 1) & 1, (kc + 1) * 32); cp_commit(); }

        uint32_t s0 = sbase + (kc & 1) * H_ST;
        #pragma unroll
        for (int ks = 0; ks < 2; ks++) {
            const uint32_t ka = ks * 32u;
            const uint32_t kb = ks * 6400u;
            uint32_t ahi[4][4], alo[4][4];
            #pragma unroll
            for (int mt = 0; mt < 4; mt++) {
                ldsm_x4(ahi[mt], s0 + H_OAH + abase[mt] + ka);
                ldsm_x4(alo[mt], s0 + H_OAL + abase[mt] + ka);
            }
            uint32_t bf[3][4];
            #pragma unroll
            for (int p = 0; p < 3; p++)
                ldsm_x4_t(bf[p], s0 + H_OB + bbase[p] + kb);
            #pragma unroll
            for (int p = 0; p < 3; p++)
                #pragma unroll
                for (int mt = 0; mt < 4; mt++) {
                    mma_f16(acc[mt][2 * p + 0], ahi[mt], bf[p]);
                    mma_f16(acc[mt][2 * p + 1], ahi[mt], bf[p] + 2);
                }
            #pragma unroll
            for (int p = 0; p < 3; p++)
                #pragma unroll
                for (int mt = 0; mt < 4; mt++) {
                    mma_f16(acc[mt][2 * p + 0], alo[mt], bf[p]);
                    mma_f16(acc[mt][2 * p + 1], alo[mt], bf[p] + 2);
                }
        }
    }

    const int ml = lane >> 2;
    const int nl = 2 * (lane & 3);
    #pragma unroll
    for (int mt = 0; mt < 4; mt++) {
        #pragma unroll
        for (int nt = 0; nt < 6; nt++) {
            int m = row0 + wm * 64 + mt * 16 + ml;
            int n = col0 + wn * 48 + nt * 8 + nl;
            float2 bv = *(const float2*)&bias[n];
            float* c = acc[mt][nt];
            if (n < qcols) {
                float v0 = (c[0] + bv.x) * 0.125f, v1 = (c[1] + bv.y) * 0.125f;
                float w0 = (c[2] + bv.x) * 0.125f, w1 = (c[3] + bv.y) * 0.125f;
                uint32_t h, l;
                split_f16(make_float2(v0, v1), h, l);
                *(uint32_t*)(Ch + (size_t)m * N + n) = h;
                *(uint32_t*)(Cl + (size_t)m * N + n) = l;
                split_f16(make_float2(w0, w1), h, l);
                *(uint32_t*)(Ch + (size_t)(m + 8) * N + n) = h;
                *(uint32_t*)(Cl + (size_t)(m + 8) * N + n) = l;
            } else {
                *(uint32_t*)(Ch + (size_t)m * N + n) =
                    pair_f16(make_float2(c[0] + bv.x, c[1] + bv.y));
                *(uint32_t*)(Ch + (size_t)(m + 8) * N + n) =
                    pair_f16(make_float2(c[2] + bv.x, c[3] + bv.y));
            }
        }
    }
}

// ===========================================================================
// Out-proj GEMM (unchanged from R14): A = attn (hi+lo), B = W_out (single).
// ===========================================================================
#define G_OAH  0
#define G_OAL  10240
#define G_OB   20480
#define G_ST   29184
#define G_SMEM (2 * G_ST)   // 58368

__global__ __launch_bounds__(256, 2)
void gemm_out(const uint16_t* __restrict__ Ah, const uint16_t* __restrict__ Al,
              const uint16_t* __restrict__ Bh,
              const float* __restrict__ bias, float* __restrict__ Cf,
              int N, int K)
{
    extern __shared__ char sm[];
    const uint32_t sbase = smem_u32(sm);

    const int tid  = threadIdx.x;
    const int lane = tid & 31;
    const int wid  = tid >> 5;
    const int wm   = wid & 3;
    const int wn   = wid >> 2;
    const int row0 = blockIdx.y * 128;
    const int col0 = blockIdx.x * 128;

    const int ar  = tid >> 1;
    const int akc = (tid & 1) * 2;
    const int br  = tid >> 3;
    const int bnc = (tid & 7) * 2;

    const uint16_t* Aph = Ah + (size_t)(row0 + ar) * K + akc * 8;
    const uint16_t* Apl = Al + (size_t)(row0 + ar) * K + akc * 8;
    const uint16_t* Bp  = Bh + (size_t)br * N + col0 + bnc * 8;

    const uint32_t sao0 = (uint32_t)(ar * 40 + akc * 8) * 2u;
    const uint32_t sao1 = sao0 + 16u;
    const uint32_t sbo0 = (uint32_t)(br * 136 + bnc * 8) * 2u;
    const uint32_t sbo1 = sbo0 + 16u;

    const int g  = lane >> 3;
    const int rr = lane & 7;
    uint32_t abase[2];
    #pragma unroll
    for (int mt = 0; mt < 2; mt++)
        abase[mt] = (uint32_t)((wm * 32 + mt * 16 + (g & 1) * 8 + rr) * 40
                               + (g >> 1) * 8) * 2u;
    uint32_t bbase[4];
    #pragma unroll
    for (int np = 0; np < 4; np++)
        bbase[np] = (uint32_t)(((g & 1) * 8 + rr) * 136
                               + wn * 64 + np * 16 + (g >> 1) * 8) * 2u;

    float acc[2][8][4];
    #pragma unroll
    for (int i = 0; i < 2; i++)
        #pragma unroll
        for (int j = 0; j < 8; j++)
            #pragma unroll
            for (int r = 0; r < 4; r++)
                acc[i][j][r] = 0.f;

    auto LOAD = [&](int st, int k0) {
        uint32_t s0 = sbase + st * G_ST;
        cp16(s0 + G_OAH + sao0, Aph + k0);
        cp16(s0 + G_OAH + sao1, Aph + k0 + 8);
        cp16(s0 + G_OAL + sao0, Apl + k0);
        cp16(s0 + G_OAL + sao1, Apl + k0 + 8);
        cp16(s0 + G_OB + sbo0, Bp + (size_t)k0 * N);
        cp16(s0 + G_OB + sbo1, Bp + (size_t)k0 * N + 8);
    };

    const int nk = K / 32;
    LOAD(0, 0);
    cp_commit();

    for (int kc = 0; kc < nk; kc++) {
        cp_wait<0>();
        __syncthreads();
        if (kc + 1 < nk) { LOAD((kc + 1) & 1, (kc + 1) * 32); cp_commit(); }

        uint32_t s0 = sbase + (kc & 1) * G_ST;
        #pragma unroll
        for (int ks = 0; ks < 2; ks++) {
            const uint32_t ka = ks * 32u;
            const uint32_t kb = ks * 4352u;
            uint32_t ahi[2][4], alo[2][4];
            ldsm_x4(ahi[0], s0 + G_OAH + abase[0] + ka);
            ldsm_x4(ahi[1], s0 + G_OAH + abase[1] + ka);
            ldsm_x4(alo[0], s0 + G_OAL + abase[0] + ka);
            ldsm_x4(alo[1], s0 + G_OAL + abase[1] + ka);
            uint32_t bf[4][4];
            #pragma unroll
            for (int np = 0; np < 4; np++)
                ldsm_x4_t(bf[np], s0 + G_OB + bbase[np] + kb);
            #pragma unroll
            for (int np = 0; np < 4; np++)
                #pragma unroll
                for (int mt = 0; mt < 2; mt++) {
                    mma_f16(acc[mt][2 * np + 0], ahi[mt], bf[np]);
                    mma_f16(acc[mt][2 * np + 1], ahi[mt], bf[np] + 2);
                }
            #pragma unroll
            for (int np = 0; np < 4; np++)
                #pragma unroll
                for (int mt = 0; mt < 2; mt++) {
                    mma_f16(acc[mt][2 * np + 0], alo[mt], bf[np]);
                    mma_f16(acc[mt][2 * np + 1], alo[mt], bf[np] + 2);
                }
        }
    }

    const int ml = lane >> 2;
    const int nl = 2 * (lane & 3);
    #pragma unroll
    for (int mt = 0; mt < 2; mt++) {
        #pragma unroll
        for (int nt = 0; nt < 8; nt++) {
            int m = row0 + wm * 32 + mt * 16 + ml;
            int n = col0 + wn * 64 + nt * 8 + nl;
            float2 bv = *(const float2*)&bias[n];
            float* c = acc[mt][nt];
            *(float2*)(Cf + (size_t)m * N + n) =
                make_float2(c[0] + bv.x, c[1] + bv.y);
            *(float2*)(Cf + (size_t)(m + 8) * N + n) =
                make_float2(c[2] + bv.x, c[3] + bv.y);
        }
    }
}

// ===========================================================================
// Flash attention: Q 2-term fp16, K/V single fp16, P SINGLE-term fp16
// (R15 change: P residual dropped -> 96 HMMA/iter instead of 128).
// ===========================================================================
#define FA_PAD  72
#define O_QHI   0
#define O_QLO   18432
#define KV_ST0  36864
#define P_K     0
#define P_V     9216
#define KV_STG  18432
#define FA_SMEM (KV_ST0 + 2 * KV_STG)   // 73728

__global__ __launch_bounds__(256)
void flash_attn_mma_kernel(const uint16_t* __restrict__ qkv_hi,
                           const uint16_t* __restrict__ qkv_lo,
                           uint16_t* __restrict__ attn_hi,
                           uint16_t* __restrict__ attn_lo)
{
    extern __shared__ char fsm[];
    const uint32_t sb = smem_u32(fsm);

    const int tid  = threadIdx.x;
    const int lane = tid & 31;
    const int wm   = tid >> 5;
    const int qt   = blockIdx.x;
    const int b    = blockIdx.y >> 4;
    const int h    = blockIdx.y & 15;

    // ---- load Q tile (hi+lo fp16, pre-scaled upstream) ----
    {
        const int r  = tid >> 1;
        const int c0 = (tid & 1) * 32;
        const uint16_t* qh = qkv_hi + (size_t)(b * SEQ + qt * 128 + r) * QKVW
                                    + h * HD + c0;
        const uint16_t* ql = qkv_lo + (size_t)(b * SEQ + qt * 128 + r) * QKVW
                                    + h * HD + c0;
        uint32_t base = (uint32_t)(r * FA_PAD + c0) * 2u;
        #pragma unroll
        for (int s = 0; s < 4; s++) {
            *(uint4*)(fsm + O_QHI + base + 16 * s) = *(const uint4*)(qh + 8 * s);
            *(uint4*)(fsm + O_QLO + base + 16 * s) = *(const uint4*)(ql + 8 * s);
        }
    }

    const int kr  = tid >> 2;
    const int kc0 = (tid & 3) * 16;
    auto LOADKV = [&](int kt, int st) {
        size_t roff = (size_t)(b * SEQ + kt * 64 + kr) * QKVW + h * HD + kc0;
        const uint16_t* gk = qkv_hi + roff + EMB;
        const uint16_t* gv = qkv_hi + roff + 2 * EMB;
        uint32_t d = sb + KV_ST0 + (uint32_t)(st * KV_STG)
                   + (uint32_t)(kr * FA_PAD + kc0) * 2u;
        cp16(d + P_K,      gk);
        cp16(d + P_K + 16, gk + 8);
        cp16(d + P_V,      gv);
        cp16(d + P_V + 16, gv + 8);
    };

    LOADKV(0, 0);
    cp_commit();
    __syncthreads();

    const int g  = lane >> 3;
    const int rr = lane & 7;
    uint32_t qhi[4][4], qlo[4][4];
    {
        uint32_t moff = (uint32_t)((wm * 16 + (g & 1) * 8 + rr) * FA_PAD) * 2u;
        #pragma unroll
        for (int t = 0; t < 4; t++) {
            uint32_t koff = (uint32_t)((g >> 1) * 8 + 16 * t) * 2u;
            ldsm_x4(qhi[t], sb + O_QHI + moff + koff);
            ldsm_x4(qlo[t], sb + O_QLO + moff + koff);
        }
    }

    const uint32_t kbase = (uint32_t)(((g >> 1) * 8 + rr) * FA_PAD + (g & 1) * 8) * 2u;
    const uint32_t vbase = (uint32_t)(((g & 1) * 8 + rr) * FA_PAD + (g >> 1) * 8) * 2u;

    float m0 = -1e30f, m1 = -1e30f, l0 = 0.f, l1 = 0.f;
    float o[8][4];
    #pragma unroll
    for (int j = 0; j < 8; j++)
        #pragma unroll
        for (int r = 0; r < 4; r++) o[j][r] = 0.f;

    for (int kt = 0; kt < SEQ / 64; kt++) {
        cp_wait<0>();
        __syncthreads();
        if (kt + 1 < SEQ / 64) { LOADKV(kt + 1, (kt + 1) & 1); cp_commit(); }

        const uint32_t stg = sb + KV_ST0 + (uint32_t)((kt & 1) * KV_STG);

        // ---- S = (Qhi + Qlo) K^T : 2-term, term-major ----
        float s[8][4];
        #pragma unroll
        for (int j = 0; j < 8; j++)
            #pragma unroll
            for (int r4 = 0; r4 < 4; r4++) s[j][r4] = 0.f;

        #pragma unroll
        for (int t = 0; t < 4; t++) {
            uint32_t kf[4][4];
            #pragma unroll
            for (int nt = 0; nt < 4; nt++) {
                uint32_t off = kbase + (uint32_t)(nt * 16 * FA_PAD + 16 * t) * 2u;
                ldsm_x4(kf[nt], stg + P_K + off);
            }
            #pragma unroll
            for (int nt = 0; nt < 4; nt++) {
                mma_f16(s[2 * nt + 0], qhi[t], kf[nt]);
                mma_f16(s[2 * nt + 1], qhi[t], kf[nt] + 2);
            }
            #pragma unroll
            for (int nt = 0; nt < 4; nt++) {
                mma_f16(s[2 * nt + 0], qlo[t], kf[nt]);
                mma_f16(s[2 * nt + 1], qlo[t], kf[nt] + 2);
            }
        }

        // ---- online softmax ----
        float mx0 = -1e30f, mx1 = -1e30f;
        #pragma unroll
        for (int j = 0; j < 8; j++) {
            mx0 = fmaxf(mx0, fmaxf(s[j][0], s[j][1]));
            mx1 = fmaxf(mx1, fmaxf(s[j][2], s[j][3]));
        }
        mx0 = fmaxf(mx0, __shfl_xor_sync(0xffffffffu, mx0, 1));
        mx0 = fmaxf(mx0, __shfl_xor_sync(0xffffffffu, mx0, 2));
        mx1 = fmaxf(mx1, __shfl_xor_sync(0xffffffffu, mx1, 1));
        mx1 = fmaxf(mx1, __shfl_xor_sync(0xffffffffu, mx1, 2));

        float mn0 = fmaxf(m0, mx0), mn1 = fmaxf(m1, mx1);
        float a0 = __expf(m0 - mn0), a1 = __expf(m1 - mn1);
        m0 = mn0; m1 = mn1;

        float sum0 = 0.f, sum1 = 0.f;
        #pragma unroll
        for (int j = 0; j < 8; j++) {
            s[j][0] = __expf(s[j][0] - mn0);
            s[j][1] = __expf(s[j][1] - mn0);
            s[j][2] = __expf(s[j][2] - mn1);
            s[j][3] = __expf(s[j][3] - mn1);
            sum0 += s[j][0] + s[j][1];
            sum1 += s[j][2] + s[j][3];
        }
        sum0 += __shfl_xor_sync(0xffffffffu, sum0, 1);
        sum0 += __shfl_xor_sync(0xffffffffu, sum0, 2);
        sum1 += __shfl_xor_sync(0xffffffffu, sum1, 1);
        sum1 += __shfl_xor_sync(0xffffffffu, sum1, 2);
        l0 = l0 * a0 + sum0;
        l1 = l1 * a1 + sum1;

        #pragma unroll
        for (int j = 0; j < 8; j++) {
            o[j][0] *= a0; o[j][1] *= a0;
            o[j][2] *= a1; o[j][3] *= a1;
        }

        // ---- o += P V : SINGLE-term fp16 P, term-major ----
        #pragma unroll
        for (int t = 0; t < 4; t++) {
            uint32_t pf[4];
            pf[0] = pair_f16(make_float2(s[2*t][0],   s[2*t][1]));
            pf[1] = pair_f16(make_float2(s[2*t][2],   s[2*t][3]));
            pf[2] = pair_f16(make_float2(s[2*t+1][0], s[2*t+1][1]));
            pf[3] = pair_f16(make_float2(s[2*t+1][2], s[2*t+1][3]));
            uint32_t vf[4][4];
            #pragma unroll
            for (int nt = 0; nt < 4; nt++) {
                uint32_t off = vbase + (uint32_t)(t * 16 * FA_PAD + nt * 16) * 2u;
                ldsm_x4_t(vf[nt], stg + P_V + off);
            }
            #pragma unroll
            for (int nt = 0; nt < 4; nt++) {
                mma_f16(o[2 * nt + 0], pf, vf[nt]);
                mma_f16(o[2 * nt + 1], pf, vf[nt] + 2);
            }
        }
    }

    // ---- epilogue: normalize, 2-term split, write planes ----
    float inv0 = 1.f / l0, inv1 = 1.f / l1;
    int row = b * SEQ + qt * 128 + wm * 16 + (lane >> 2);
    size_t e0 = (size_t)row * EMB + h * HD + 2 * (lane & 3);
    #pragma unroll
    for (int j = 0; j < 8; j++) {
        uint32_t hh, ll;
        split_f16(make_float2(o[j][0] * inv0, o[j][1] * inv0), hh, ll);
        *(uint32_t*)(attn_hi + e0 + 8 * j) = hh;
        *(uint32_t*)(attn_lo + e0 + 8 * j) = ll;
        split_f16(make_float2(o[j][2] * inv1, o[j][3] * inv1), hh, ll);
        *(uint32_t*)(attn_hi + e0 + (size_t)8 * EMB + 8 * j) = hh;
        *(uint32_t*)(attn_lo + e0 + (size_t)8 * EMB + 8 * j) = ll;
    }
}

// ---------------------------------------------------------------------------
extern "C" void kernel_launch(void* const* d_in, const int* in_sizes, int n_in,
                              void* d_out, int out_size)
{
    (void)in_sizes; (void)n_in; (void)out_size;
    const float* x     = (const float*)d_in[0];
    const float* w_qkv = (const float*)d_in[1];
    const float* b_qkv = (const float*)d_in[2];
    const float* w_out = (const float*)d_in[3];
    const float* b_out = (const float*)d_in[4];
    float* out = (float*)d_out;

    uint16_t *x_hi, *x_lo, *wq, *wo, *qkv_hi, *qkv_lo, *attn_hi, *attn_lo;
    cudaGetSymbolAddress((void**)&x_hi,   g_x_hi);
    cudaGetSymbolAddress((void**)&x_lo,   g_x_lo);
    cudaGetSymbolAddress((void**)&wq,     g_wqkv);
    cudaGetSymbolAddress((void**)&wo,     g_wout);
    cudaGetSymbolAddress((void**)&qkv_hi, g_qkv_hi);
    cudaGetSymbolAddress((void**)&qkv_lo, g_qkv_lo);
    cudaGetSymbolAddress((void**)&attn_hi, g_attn_hi);
    cudaGetSymbolAddress((void**)&attn_lo, g_attn_lo);

    cudaFuncSetAttribute(gemm_qkv,
                         cudaFuncAttributeMaxDynamicSharedMemorySize, H_SMEM);
    cudaFuncSetAttribute(gemm_out,
                         cudaFuncAttributeMaxDynamicSharedMemorySize, G_SMEM);
    cudaFuncSetAttribute(flash_attn_mma_kernel,
                         cudaFuncAttributeMaxDynamicSharedMemorySize, FA_SMEM);

    // 0) merged converts
    const int n4_total = N4_X + N4_WQ + N4_WO;
    split_all_kernel<<<(n4_total + 255) / 256, 256>>>(
        (const float4*)x, (const float4*)w_qkv, (const float4*)w_out,
        x_hi, x_lo, wq, wo);

    // 1) QKV projection (2-term fp16) -> Q split planes, K/V single plane
    gemm_qkv<<<dim3(QKVW / 192, NROWS / 128), 256, H_SMEM>>>(
        x_hi, x_lo, wq, b_qkv, qkv_hi, qkv_lo, QKVW, EMB, EMB);

    // 2) attention (QK 2-term, PV 1-term fp16) -> split planes
    flash_attn_mma_kernel<<<dim3(SEQ / 128, BATCH * HEADS), 256, FA_SMEM>>>(
        qkv_hi, qkv_lo, attn_hi, attn_lo);

    // 3) output projection (2-term fp16) -> fp32 out
    gemm_out<<<dim3(EMB / 128, NROWS / 128), 256, G_SMEM>>>(
        attn_hi, attn_lo, wo, b_out, out, EMB, EMB);
}

// round 16
// speedup vs baseline: 1.7677x; 1.0676x over previous
#include <cuda_runtime.h>
#include <cuda_fp16.h>
#include <cstdint>

#define EMB   1024
#define HEADS 16
#define HD    64
#define BATCH 4
#define SEQ   2048
#define NROWS (BATCH * SEQ)      // 8192
#define QKVW  (3 * EMB)          // 3072

// ---------------------------------------------------------------------------
// Global scratch: fp16 planes.
// ---------------------------------------------------------------------------
__device__ __align__(128) uint16_t g_x_hi[(size_t)NROWS * EMB];
__device__ __align__(128) uint16_t g_x_lo[(size_t)NROWS * EMB];
__device__ __align__(128) uint16_t g_wqkv[(size_t)EMB * QKVW];
__device__ __align__(128) uint16_t g_wout[(size_t)EMB * EMB];
__device__ __align__(128) uint16_t g_qkv_hi[(size_t)NROWS * QKVW];
__device__ __align__(128) uint16_t g_qkv_lo[(size_t)NROWS * QKVW];   // Q residual only
__device__ __align__(128) uint16_t g_attn[(size_t)NROWS * EMB];      // single plane

// ---------------------------------------------------------------------------
// Helpers
// ---------------------------------------------------------------------------
__device__ __forceinline__ uint32_t smem_u32(const void* p) {
    uint32_t a;
    asm("{ .reg .u64 t; cvta.to.shared.u64 t, %1; cvt.u32.u64 %0, t; }"
        : "=r"(a) : "l"(p));
    return a;
}
__device__ __forceinline__ void split_f16(float2 v, uint32_t& hi, uint32_t& lo) {
    __half2 h = __floats2half2_rn(v.x, v.y);
    float2 hf = __half22float2(h);
    __half2 l = __floats2half2_rn(v.x - hf.x, v.y - hf.y);
    hi = *(uint32_t*)&h;
    lo = *(uint32_t*)&l;
}
__device__ __forceinline__ uint32_t pair_f16(float2 v) {
    __half2 h = __floats2half2_rn(v.x, v.y);
    return *(uint32_t*)&h;
}
__device__ __forceinline__ void ldsm_x4(uint32_t* r, uint32_t addr) {
    asm volatile("ldmatrix.sync.aligned.m8n8.x4.shared.b16 {%0,%1,%2,%3}, [%4];"
                 : "=r"(r[0]), "=r"(r[1]), "=r"(r[2]), "=r"(r[3]) : "r"(addr));
}
__device__ __forceinline__ void ldsm_x4_t(uint32_t* r, uint32_t addr) {
    asm volatile("ldmatrix.sync.aligned.m8n8.x4.trans.shared.b16 {%0,%1,%2,%3}, [%4];"
                 : "=r"(r[0]), "=r"(r[1]), "=r"(r[2]), "=r"(r[3]) : "r"(addr));
}
__device__ __forceinline__ void mma_f16(float* c, const uint32_t* a,
                                        const uint32_t* b) {
    asm volatile(
        "mma.sync.aligned.m16n8k16.row.col.f32.f16.f16.f32 "
        "{%0,%1,%2,%3}, {%4,%5,%6,%7}, {%8,%9}, {%0,%1,%2,%3};"
        : "+f"(c[0]), "+f"(c[1]), "+f"(c[2]), "+f"(c[3])
        : "r"(a[0]), "r"(a[1]), "r"(a[2]), "r"(a[3]), "r"(b[0]), "r"(b[1]));
}
__device__ __forceinline__ void cp16(uint32_t s, const void* g) {
    asm volatile("cp.async.cg.shared.global [%0], [%1], 16;" :: "r"(s), "l"(g));
}
__device__ __forceinline__ void cp_commit() {
    asm volatile("cp.async.commit_group;");
}
template<int N> __device__ __forceinline__ void cp_wait() {
    asm volatile("cp.async.wait_group %0;" :: "n"(N));
}

// ---------------------------------------------------------------------------
// Merged converts: x -> fp16 split planes; W_qkv, W_out -> single fp16.
// ---------------------------------------------------------------------------
#define N4_X  (NROWS * EMB / 4)
#define N4_WQ (EMB * QKVW / 4)
#define N4_WO (EMB * EMB / 4)

__global__ void split_all_kernel(const float4* __restrict__ x,
                                 const float4* __restrict__ wq,
                                 const float4* __restrict__ wo,
                                 uint16_t* __restrict__ x_hi, uint16_t* __restrict__ x_lo,
                                 uint16_t* __restrict__ wq_h, uint16_t* __restrict__ wo_h)
{
    int i = blockIdx.x * blockDim.x + threadIdx.x;
    if (i < N4_X) {
        float4 v = x[i];
        uint32_t h0, l0, h1, l1;
        split_f16(make_float2(v.x, v.y), h0, l0);
        split_f16(make_float2(v.z, v.w), h1, l1);
        ((uint2*)x_hi)[i] = make_uint2(h0, h1);
        ((uint2*)x_lo)[i] = make_uint2(l0, l1);
    } else if (i < N4_X + N4_WQ) {
        int j = i - N4_X;
        float4 v = wq[j];
        ((uint2*)wq_h)[j] = make_uint2(pair_f16(make_float2(v.x, v.y)),
                                       pair_f16(make_float2(v.z, v.w)));
    } else if (i < N4_X + N4_WQ + N4_WO) {
        int j = i - N4_X - N4_WQ;
        float4 v = wo[j];
        ((uint2*)wo_h)[j] = make_uint2(pair_f16(make_float2(v.x, v.y)),
                                       pair_f16(make_float2(v.z, v.w)));
    }
}

// ===========================================================================
// QKV GEMM (unchanged): A = x (hi+lo), B = W_qkv (single). 2-term.
// ===========================================================================
#define H_OAH  0
#define H_OAL  10240
#define H_OB   20480
#define H_ST   33280
#define H_SMEM (2 * H_ST)   // 66560

__global__ __launch_bounds__(256)
void gemm_qkv(const uint16_t* __restrict__ Ah, const uint16_t* __restrict__ Al,
              const uint16_t* __restrict__ Bh,
              const float* __restrict__ bias,
              uint16_t* __restrict__ Ch, uint16_t* __restrict__ Cl,
              int N, int K, int qcols)
{
    extern __shared__ char sm[];
    const uint32_t sbase = smem_u32(sm);

    const int tid  = threadIdx.x;
    const int lane = tid & 31;
    const int wid  = tid >> 5;
    const int wm   = wid & 1;
    const int wn   = wid >> 1;
    const int row0 = blockIdx.y * 128;
    const int col0 = blockIdx.x * 192;

    const int ar = tid >> 1;
    const uint16_t* Aph = Ah + (size_t)(row0 + ar) * K + (tid & 1) * 16;
    const uint16_t* Apl = Al + (size_t)(row0 + ar) * K + (tid & 1) * 16;
    const uint32_t sao = (uint32_t)(ar * 80 + (tid & 1) * 32);
    const int br = tid >> 3;
    const uint16_t* Bp = Bh + (size_t)br * N + col0 + (tid & 7) * 8;
    const uint32_t sbo = (uint32_t)(br * 400 + (tid & 7) * 16);

    const int g  = lane >> 3;
    const int rr = lane & 7;
    uint32_t abase[4];
    #pragma unroll
    for (int mt = 0; mt < 4; mt++)
        abase[mt] = (uint32_t)((wm * 64 + mt * 16 + (g & 1) * 8 + rr) * 40
                               + (g >> 1) * 8) * 2u;
    uint32_t bbase[3];
    #pragma unroll
    for (int p = 0; p < 3; p++)
        bbase[p] = (uint32_t)(((g & 1) * 8 + rr) * 200
                              + wn * 48 + p * 16 + (g >> 1) * 8) * 2u;

    float acc[4][6][4];
    #pragma unroll
    for (int i = 0; i < 4; i++)
        #pragma unroll
        for (int j = 0; j < 6; j++)
            #pragma unroll
            for (int r = 0; r < 4; r++)
                acc[i][j][r] = 0.f;

    auto LOAD = [&](int st, int k0) {
        uint32_t s0 = sbase + st * H_ST;
        cp16(s0 + H_OAH + sao,      Aph + k0);
        cp16(s0 + H_OAH + sao + 16, Aph + k0 + 8);
        cp16(s0 + H_OAL + sao,      Apl + k0);
        cp16(s0 + H_OAL + sao + 16, Apl + k0 + 8);
        const uint16_t* b = Bp + (size_t)k0 * N;
        #pragma unroll
        for (int j = 0; j < 3; j++)
            cp16(s0 + H_OB + sbo + 128 * j, b + 64 * j);
    };

    const int nk = K / 32;
    LOAD(0, 0);
    cp_commit();

    for (int kc = 0; kc < nk; kc++) {
        cp_wait<0>();
        __syncthreads();
        if (kc + 1 < nk) { LOAD((kc + 1) & 1, (kc + 1) * 32); cp_commit(); }

        uint32_t s0 = sbase + (kc & 1) * H_ST;
        #pragma unroll
        for (int ks = 0; ks < 2; ks++) {
            const uint32_t ka = ks * 32u;
            const uint32_t kb = ks * 6400u;
            uint32_t ahi[4][4], alo[4][4];
            #pragma unroll
            for (int mt = 0; mt < 4; mt++) {
                ldsm_x4(ahi[mt], s0 + H_OAH + abase[mt] + ka);
                ldsm_x4(alo[mt], s0 + H_OAL + abase[mt] + ka);
            }
            uint32_t bf[3][4];
            #pragma unroll
            for (int p = 0; p < 3; p++)
                ldsm_x4_t(bf[p], s0 + H_OB + bbase[p] + kb);
            #pragma unroll
            for (int p = 0; p < 3; p++)
                #pragma unroll
                for (int mt = 0; mt < 4; mt++) {
                    mma_f16(acc[mt][2 * p + 0], ahi[mt], bf[p]);
                    mma_f16(acc[mt][2 * p + 1], ahi[mt], bf[p] + 2);
                }
            #pragma unroll
            for (int p = 0; p < 3; p++)
                #pragma unroll
                for (int mt = 0; mt < 4; mt++) {
                    mma_f16(acc[mt][2 * p + 0], alo[mt], bf[p]);
                    mma_f16(acc[mt][2 * p + 1], alo[mt], bf[p] + 2);
                }
        }
    }

    const int ml = lane >> 2;
    const int nl = 2 * (lane & 3);
    #pragma unroll
    for (int mt = 0; mt < 4; mt++) {
        #pragma unroll
        for (int nt = 0; nt < 6; nt++) {
            int m = row0 + wm * 64 + mt * 16 + ml;
            int n = col0 + wn * 48 + nt * 8 + nl;
            float2 bv = *(const float2*)&bias[n];
            float* c = acc[mt][nt];
            if (n < qcols) {
                float v0 = (c[0] + bv.x) * 0.125f, v1 = (c[1] + bv.y) * 0.125f;
                float w0 = (c[2] + bv.x) * 0.125f, w1 = (c[3] + bv.y) * 0.125f;
                uint32_t h, l;
                split_f16(make_float2(v0, v1), h, l);
                *(uint32_t*)(Ch + (size_t)m * N + n) = h;
                *(uint32_t*)(Cl + (size_t)m * N + n) = l;
                split_f16(make_float2(w0, w1), h, l);
                *(uint32_t*)(Ch + (size_t)(m + 8) * N + n) = h;
                *(uint32_t*)(Cl + (size_t)(m + 8) * N + n) = l;
            } else {
                *(uint32_t*)(Ch + (size_t)m * N + n) =
                    pair_f16(make_float2(c[0] + bv.x, c[1] + bv.y));
                *(uint32_t*)(Ch + (size_t)(m + 8) * N + n) =
                    pair_f16(make_float2(c[2] + bv.x, c[3] + bv.y));
            }
        }
    }
}

// ===========================================================================
// Out-proj GEMM (R16: 1-term): A = attn (single fp16), B = W_out (single).
// 128x128 tile, 8 warps (4m x 2n), K-chunk 32, 2-stage cp.async.
// smem/stage: A 10240 + B 8704 = 18944; 2 stages = 37888 -> 2+ CTAs/SM.
// ===========================================================================
#define G_OA   0
#define G_OB   10240
#define G_ST   18944
#define G_SMEM (2 * G_ST)   // 37888

__global__ __launch_bounds__(256, 2)
void gemm_out(const uint16_t* __restrict__ Ah,
              const uint16_t* __restrict__ Bh,
              const float* __restrict__ bias, float* __restrict__ Cf,
              int N, int K)
{
    extern __shared__ char sm[];
    const uint32_t sbase = smem_u32(sm);

    const int tid  = threadIdx.x;
    const int lane = tid & 31;
    const int wid  = tid >> 5;
    const int wm   = wid & 3;
    const int wn   = wid >> 2;
    const int row0 = blockIdx.y * 128;
    const int col0 = blockIdx.x * 128;

    const int ar  = tid >> 1;
    const int akc = (tid & 1) * 2;
    const int br  = tid >> 3;
    const int bnc = (tid & 7) * 2;

    const uint16_t* Ap = Ah + (size_t)(row0 + ar) * K + akc * 8;
    const uint16_t* Bp = Bh + (size_t)br * N + col0 + bnc * 8;

    const uint32_t sao0 = (uint32_t)(ar * 40 + akc * 8) * 2u;
    const uint32_t sao1 = sao0 + 16u;
    const uint32_t sbo0 = (uint32_t)(br * 136 + bnc * 8) * 2u;
    const uint32_t sbo1 = sbo0 + 16u;

    const int g  = lane >> 3;
    const int rr = lane & 7;
    uint32_t abase[2];
    #pragma unroll
    for (int mt = 0; mt < 2; mt++)
        abase[mt] = (uint32_t)((wm * 32 + mt * 16 + (g & 1) * 8 + rr) * 40
                               + (g >> 1) * 8) * 2u;
    uint32_t bbase[4];
    #pragma unroll
    for (int np = 0; np < 4; np++)
        bbase[np] = (uint32_t)(((g & 1) * 8 + rr) * 136
                               + wn * 64 + np * 16 + (g >> 1) * 8) * 2u;

    float acc[2][8][4];
    #pragma unroll
    for (int i = 0; i < 2; i++)
        #pragma unroll
        for (int j = 0; j < 8; j++)
            #pragma unroll
            for (int r = 0; r < 4; r++)
                acc[i][j][r] = 0.f;

    auto LOAD = [&](int st, int k0) {
        uint32_t s0 = sbase + st * G_ST;
        cp16(s0 + G_OA + sao0, Ap + k0);
        cp16(s0 + G_OA + sao1, Ap + k0 + 8);
        cp16(s0 + G_OB + sbo0, Bp + (size_t)k0 * N);
        cp16(s0 + G_OB + sbo1, Bp + (size_t)k0 * N + 8);
    };

    const int nk = K / 32;
    LOAD(0, 0);
    cp_commit();

    for (int kc = 0; kc < nk; kc++) {
        cp_wait<0>();
        __syncthreads();
        if (kc + 1 < nk) { LOAD((kc + 1) & 1, (kc + 1) * 32); cp_commit(); }

        uint32_t s0 = sbase + (kc & 1) * G_ST;
        #pragma unroll
        for (int ks = 0; ks < 2; ks++) {
            const uint32_t ka = ks * 32u;
            const uint32_t kb = ks * 4352u;
            uint32_t af[2][4];
            ldsm_x4(af[0], s0 + G_OA + abase[0] + ka);
            ldsm_x4(af[1], s0 + G_OA + abase[1] + ka);
            uint32_t bf[4][4];
            #pragma unroll
            for (int np = 0; np < 4; np++)
                ldsm_x4_t(bf[np], s0 + G_OB + bbase[np] + kb);
            #pragma unroll
            for (int np = 0; np < 4; np++)
                #pragma unroll
                for (int mt = 0; mt < 2; mt++) {
                    mma_f16(acc[mt][2 * np + 0], af[mt], bf[np]);
                    mma_f16(acc[mt][2 * np + 1], af[mt], bf[np] + 2);
                }
        }
    }

    const int ml = lane >> 2;
    const int nl = 2 * (lane & 3);
    #pragma unroll
    for (int mt = 0; mt < 2; mt++) {
        #pragma unroll
        for (int nt = 0; nt < 8; nt++) {
            int m = row0 + wm * 32 + mt * 16 + ml;
            int n = col0 + wn * 64 + nt * 8 + nl;
            float2 bv = *(const float2*)&bias[n];
            float* c = acc[mt][nt];
            *(float2*)(Cf + (size_t)m * N + n) =
                make_float2(c[0] + bv.x, c[1] + bv.y);
            *(float2*)(Cf + (size_t)(m + 8) * N + n) =
                make_float2(c[2] + bv.x, c[3] + bv.y);
        }
    }
}

// ===========================================================================
// Flash attention: Q 2-term fp16, K/V single fp16, P single fp16.
// R16: output written as SINGLE rn-f16 plane (no residual).
// ===========================================================================
#define FA_PAD  72
#define O_QHI   0
#define O_QLO   18432
#define KV_ST0  36864
#define P_K     0
#define P_V     9216
#define KV_STG  18432
#define FA_SMEM (KV_ST0 + 2 * KV_STG)   // 73728

__global__ __launch_bounds__(256)
void flash_attn_mma_kernel(const uint16_t* __restrict__ qkv_hi,
                           const uint16_t* __restrict__ qkv_lo,
                           uint16_t* __restrict__ attn)
{
    extern __shared__ char fsm[];
    const uint32_t sb = smem_u32(fsm);

    const int tid  = threadIdx.x;
    const int lane = tid & 31;
    const int wm   = tid >> 5;
    const int qt   = blockIdx.x;
    const int b    = blockIdx.y >> 4;
    const int h    = blockIdx.y & 15;

    // ---- load Q tile (hi+lo fp16, pre-scaled upstream) ----
    {
        const int r  = tid >> 1;
        const int c0 = (tid & 1) * 32;
        const uint16_t* qh = qkv_hi + (size_t)(b * SEQ + qt * 128 + r) * QKVW
                                    + h * HD + c0;
        const uint16_t* ql = qkv_lo + (size_t)(b * SEQ + qt * 128 + r) * QKVW
                                    + h * HD + c0;
        uint32_t base = (uint32_t)(r * FA_PAD + c0) * 2u;
        #pragma unroll
        for (int s = 0; s < 4; s++) {
            *(uint4*)(fsm + O_QHI + base + 16 * s) = *(const uint4*)(qh + 8 * s);
            *(uint4*)(fsm + O_QLO + base + 16 * s) = *(const uint4*)(ql + 8 * s);
        }
    }

    const int kr  = tid >> 2;
    const int kc0 = (tid & 3) * 16;
    auto LOADKV = [&](int kt, int st) {
        size_t roff = (size_t)(b * SEQ + kt * 64 + kr) * QKVW + h * HD + kc0;
        const uint16_t* gk = qkv_hi + roff + EMB;
        const uint16_t* gv = qkv_hi + roff + 2 * EMB;
        uint32_t d = sb + KV_ST0 + (uint32_t)(st * KV_STG)
                   + (uint32_t)(kr * FA_PAD + kc0) * 2u;
        cp16(d + P_K,      gk);
        cp16(d + P_K + 16, gk + 8);
        cp16(d + P_V,      gv);
        cp16(d + P_V + 16, gv + 8);
    };

    LOADKV(0, 0);
    cp_commit();
    __syncthreads();

    const int g  = lane >> 3;
    const int rr = lane & 7;
    uint32_t qhi[4][4], qlo[4][4];
    {
        uint32_t moff = (uint32_t)((wm * 16 + (g & 1) * 8 + rr) * FA_PAD) * 2u;
        #pragma unroll
        for (int t = 0; t < 4; t++) {
            uint32_t koff = (uint32_t)((g >> 1) * 8 + 16 * t) * 2u;
            ldsm_x4(qhi[t], sb + O_QHI + moff + koff);
            ldsm_x4(qlo[t], sb + O_QLO + moff + koff);
        }
    }

    const uint32_t kbase = (uint32_t)(((g >> 1) * 8 + rr) * FA_PAD + (g & 1) * 8) * 2u;
    const uint32_t vbase = (uint32_t)(((g & 1) * 8 + rr) * FA_PAD + (g >> 1) * 8) * 2u;

    float m0 = -1e30f, m1 = -1e30f, l0 = 0.f, l1 = 0.f;
    float o[8][4];
    #pragma unroll
    for (int j = 0; j < 8; j++)
        #pragma unroll
        for (int r = 0; r < 4; r++) o[j][r] = 0.f;

    for (int kt = 0; kt < SEQ / 64; kt++) {
        cp_wait<0>();
        __syncthreads();
        if (kt + 1 < SEQ / 64) { LOADKV(kt + 1, (kt + 1) & 1); cp_commit(); }

        const uint32_t stg = sb + KV_ST0 + (uint32_t)((kt & 1) * KV_STG);

        // ---- S = (Qhi + Qlo) K^T : 2-term, term-major ----
        float s[8][4];
        #pragma unroll
        for (int j = 0; j < 8; j++)
            #pragma unroll
            for (int r4 = 0; r4 < 4; r4++) s[j][r4] = 0.f;

        #pragma unroll
        for (int t = 0; t < 4; t++) {
            uint32_t kf[4][4];
            #pragma unroll
            for (int nt = 0; nt < 4; nt++) {
                uint32_t off = kbase + (uint32_t)(nt * 16 * FA_PAD + 16 * t) * 2u;
                ldsm_x4(kf[nt], stg + P_K + off);
            }
            #pragma unroll
            for (int nt = 0; nt < 4; nt++) {
                mma_f16(s[2 * nt + 0], qhi[t], kf[nt]);
                mma_f16(s[2 * nt + 1], qhi[t], kf[nt] + 2);
            }
            #pragma unroll
            for (int nt = 0; nt < 4; nt++) {
                mma_f16(s[2 * nt + 0], qlo[t], kf[nt]);
                mma_f16(s[2 * nt + 1], qlo[t], kf[nt] + 2);
            }
        }

        // ---- online softmax ----
        float mx0 = -1e30f, mx1 = -1e30f;
        #pragma unroll
        for (int j = 0; j < 8; j++) {
            mx0 = fmaxf(mx0, fmaxf(s[j][0], s[j][1]));
            mx1 = fmaxf(mx1, fmaxf(s[j][2], s[j][3]));
        }
        mx0 = fmaxf(mx0, __shfl_xor_sync(0xffffffffu, mx0, 1));
        mx0 = fmaxf(mx0, __shfl_xor_sync(0xffffffffu, mx0, 2));
        mx1 = fmaxf(mx1, __shfl_xor_sync(0xffffffffu, mx1, 1));
        mx1 = fmaxf(mx1, __shfl_xor_sync(0xffffffffu, mx1, 2));

        float mn0 = fmaxf(m0, mx0), mn1 = fmaxf(m1, mx1);
        float a0 = __expf(m0 - mn0), a1 = __expf(m1 - mn1);
        m0 = mn0; m1 = mn1;

        float sum0 = 0.f, sum1 = 0.f;
        #pragma unroll
        for (int j = 0; j < 8; j++) {
            s[j][0] = __expf(s[j][0] - mn0);
            s[j][1] = __expf(s[j][1] - mn0);
            s[j][2] = __expf(s[j][2] - mn1);
            s[j][3] = __expf(s[j][3] - mn1);
            sum0 += s[j][0] + s[j][1];
            sum1 += s[j][2] + s[j][3];
        }
        sum0 += __shfl_xor_sync(0xffffffffu, sum0, 1);
        sum0 += __shfl_xor_sync(0xffffffffu, sum0, 2);
        sum1 += __shfl_xor_sync(0xffffffffu, sum1, 1);
        sum1 += __shfl_xor_sync(0xffffffffu, sum1, 2);
        l0 = l0 * a0 + sum0;
        l1 = l1 * a1 + sum1;

        #pragma unroll
        for (int j = 0; j < 8; j++) {
            o[j][0] *= a0; o[j][1] *= a0;
            o[j][2] *= a1; o[j][3] *= a1;
        }

        // ---- o += P V : single-term fp16 P, term-major ----
        #pragma unroll
        for (int t = 0; t < 4; t++) {
            uint32_t pf[4];
            pf[0] = pair_f16(make_float2(s[2*t][0],   s[2*t][1]));
            pf[1] = pair_f16(make_float2(s[2*t][2],   s[2*t][3]));
            pf[2] = pair_f16(make_float2(s[2*t+1][0], s[2*t+1][1]));
            pf[3] = pair_f16(make_float2(s[2*t+1][2], s[2*t+1][3]));
            uint32_t vf[4][4];
            #pragma unroll
            for (int nt = 0; nt < 4; nt++) {
                uint32_t off = vbase + (uint32_t)(t * 16 * FA_PAD + nt * 16) * 2u;
                ldsm_x4_t(vf[nt], stg + P_V + off);
            }
            #pragma unroll
            for (int nt = 0; nt < 4; nt++) {
                mma_f16(o[2 * nt + 0], pf, vf[nt]);
                mma_f16(o[2 * nt + 1], pf, vf[nt] + 2);
            }
        }
    }

    // ---- epilogue: normalize, single rn-f16 plane ----
    float inv0 = 1.f / l0, inv1 = 1.f / l1;
    int row = b * SEQ + qt * 128 + wm * 16 + (lane >> 2);
    size_t e0 = (size_t)row * EMB + h * HD + 2 * (lane & 3);
    #pragma unroll
    for (int j = 0; j < 8; j++) {
        *(uint32_t*)(attn + e0 + 8 * j) =
            pair_f16(make_float2(o[j][0] * inv0, o[j][1] * inv0));
        *(uint32_t*)(attn + e0 + (size_t)8 * EMB + 8 * j) =
            pair_f16(make_float2(o[j][2] * inv1, o[j][3] * inv1));
    }
}

// ---------------------------------------------------------------------------
extern "C" void kernel_launch(void* const* d_in, const int* in_sizes, int n_in,
                              void* d_out, int out_size)
{
    (void)in_sizes; (void)n_in; (void)out_size;
    const float* x     = (const float*)d_in[0];
    const float* w_qkv = (const float*)d_in[1];
    const float* b_qkv = (const float*)d_in[2];
    const float* w_out = (const float*)d_in[3];
    const float* b_out = (const float*)d_in[4];
    float* out = (float*)d_out;

    uint16_t *x_hi, *x_lo, *wq, *wo, *qkv_hi, *qkv_lo, *attn;
    cudaGetSymbolAddress((void**)&x_hi,   g_x_hi);
    cudaGetSymbolAddress((void**)&x_lo,   g_x_lo);
    cudaGetSymbolAddress((void**)&wq,     g_wqkv);
    cudaGetSymbolAddress((void**)&wo,     g_wout);
    cudaGetSymbolAddress((void**)&qkv_hi, g_qkv_hi);
    cudaGetSymbolAddress((void**)&qkv_lo, g_qkv_lo);
    cudaGetSymbolAddress((void**)&attn,   g_attn);

    cudaFuncSetAttribute(gemm_qkv,
                         cudaFuncAttributeMaxDynamicSharedMemorySize, H_SMEM);
    cudaFuncSetAttribute(gemm_out,
                         cudaFuncAttributeMaxDynamicSharedMemorySize, G_SMEM);
    cudaFuncSetAttribute(flash_attn_mma_kernel,
                         cudaFuncAttributeMaxDynamicSharedMemorySize, FA_SMEM);

    // 0) merged converts
    const int n4_total = N4_X + N4_WQ + N4_WO;
    split_all_kernel<<<(n4_total + 255) / 256, 256>>>(
        (const float4*)x, (const float4*)w_qkv, (const float4*)w_out,
        x_hi, x_lo, wq, wo);

    // 1) QKV projection (2-term fp16) -> Q split planes, K/V single plane
    gemm_qkv<<<dim3(QKVW / 192, NROWS / 128), 256, H_SMEM>>>(
        x_hi, x_lo, wq, b_qkv, qkv_hi, qkv_lo, QKVW, EMB, EMB);

    // 2) attention (QK 2-term, PV 1-term) -> single fp16 plane
    flash_attn_mma_kernel<<<dim3(SEQ / 128, BATCH * HEADS), 256, FA_SMEM>>>(
        qkv_hi, qkv_lo, attn);

    // 3) output projection (1-term fp16) -> fp32 out
    gemm_out<<<dim3(EMB / 128, NROWS / 128), 256, G_SMEM>>>(
        attn, wo, b_out, out, EMB, EMB);
}

// round 17
// speedup vs baseline: 1.8949x; 1.0720x over previous
#include <cuda_runtime.h>
#include <cuda_fp16.h>
#include <cstdint>

#define EMB   1024
#define HEADS 16
#define HD    64
#define BATCH 4
#define SEQ   2048
#define NROWS (BATCH * SEQ)      // 8192
#define QKVW  (3 * EMB)          // 3072

// ---------------------------------------------------------------------------
// Global scratch: fp16 planes. x keeps hi+lo (2-term QKV GEMM); everything
// downstream is single-plane fp16.
// ---------------------------------------------------------------------------
__device__ __align__(128) uint16_t g_x_hi[(size_t)NROWS * EMB];
__device__ __align__(128) uint16_t g_x_lo[(size_t)NROWS * EMB];
__device__ __align__(128) uint16_t g_wqkv[(size_t)EMB * QKVW];
__device__ __align__(128) uint16_t g_wout[(size_t)EMB * EMB];
__device__ __align__(128) uint16_t g_qkv[(size_t)NROWS * QKVW];
__device__ __align__(128) uint16_t g_attn[(size_t)NROWS * EMB];

// ---------------------------------------------------------------------------
// Helpers
// ---------------------------------------------------------------------------
__device__ __forceinline__ uint32_t smem_u32(const void* p) {
    uint32_t a;
    asm("{ .reg .u64 t; cvta.to.shared.u64 t, %1; cvt.u32.u64 %0, t; }"
        : "=r"(a) : "l"(p));
    return a;
}
__device__ __forceinline__ void split_f16(float2 v, uint32_t& hi, uint32_t& lo) {
    __half2 h = __floats2half2_rn(v.x, v.y);
    float2 hf = __half22float2(h);
    __half2 l = __floats2half2_rn(v.x - hf.x, v.y - hf.y);
    hi = *(uint32_t*)&h;
    lo = *(uint32_t*)&l;
}
__device__ __forceinline__ uint32_t pair_f16(float2 v) {
    __half2 h = __floats2half2_rn(v.x, v.y);
    return *(uint32_t*)&h;
}
__device__ __forceinline__ void ldsm_x4(uint32_t* r, uint32_t addr) {
    asm volatile("ldmatrix.sync.aligned.m8n8.x4.shared.b16 {%0,%1,%2,%3}, [%4];"
                 : "=r"(r[0]), "=r"(r[1]), "=r"(r[2]), "=r"(r[3]) : "r"(addr));
}
__device__ __forceinline__ void ldsm_x4_t(uint32_t* r, uint32_t addr) {
    asm volatile("ldmatrix.sync.aligned.m8n8.x4.trans.shared.b16 {%0,%1,%2,%3}, [%4];"
                 : "=r"(r[0]), "=r"(r[1]), "=r"(r[2]), "=r"(r[3]) : "r"(addr));
}
__device__ __forceinline__ void mma_f16(float* c, const uint32_t* a,
                                        const uint32_t* b) {
    asm volatile(
        "mma.sync.aligned.m16n8k16.row.col.f32.f16.f16.f32 "
        "{%0,%1,%2,%3}, {%4,%5,%6,%7}, {%8,%9}, {%0,%1,%2,%3};"
        : "+f"(c[0]), "+f"(c[1]), "+f"(c[2]), "+f"(c[3])
        : "r"(a[0]), "r"(a[1]), "r"(a[2]), "r"(a[3]), "r"(b[0]), "r"(b[1]));
}
__device__ __forceinline__ void cp16(uint32_t s, const void* g) {
    asm volatile("cp.async.cg.shared.global [%0], [%1], 16;" :: "r"(s), "l"(g));
}
__device__ __forceinline__ void cp_commit() {
    asm volatile("cp.async.commit_group;");
}
template<int N> __device__ __forceinline__ void cp_wait() {
    asm volatile("cp.async.wait_group %0;" :: "n"(N));
}

// ---------------------------------------------------------------------------
// Merged converts: x -> fp16 split planes; W_qkv, W_out -> single fp16.
// ---------------------------------------------------------------------------
#define N4_X  (NROWS * EMB / 4)
#define N4_WQ (EMB * QKVW / 4)
#define N4_WO (EMB * EMB / 4)

__global__ void split_all_kernel(const float4* __restrict__ x,
                                 const float4* __restrict__ wq,
                                 const float4* __restrict__ wo,
                                 uint16_t* __restrict__ x_hi, uint16_t* __restrict__ x_lo,
                                 uint16_t* __restrict__ wq_h, uint16_t* __restrict__ wo_h)
{
    int i = blockIdx.x * blockDim.x + threadIdx.x;
    if (i < N4_X) {
        float4 v = x[i];
        uint32_t h0, l0, h1, l1;
        split_f16(make_float2(v.x, v.y), h0, l0);
        split_f16(make_float2(v.z, v.w), h1, l1);
        ((uint2*)x_hi)[i] = make_uint2(h0, h1);
        ((uint2*)x_lo)[i] = make_uint2(l0, l1);
    } else if (i < N4_X + N4_WQ) {
        int j = i - N4_X;
        float4 v = wq[j];
        ((uint2*)wq_h)[j] = make_uint2(pair_f16(make_float2(v.x, v.y)),
                                       pair_f16(make_float2(v.z, v.w)));
    } else if (i < N4_X + N4_WQ + N4_WO) {
        int j = i - N4_X - N4_WQ;
        float4 v = wo[j];
        ((uint2*)wo_h)[j] = make_uint2(pair_f16(make_float2(v.x, v.y)),
                                       pair_f16(make_float2(v.z, v.w)));
    }
}

// ===========================================================================
// QKV GEMM: A = x (hi+lo), B = W_qkv (single). 2-term MMA.
// R17: single fp16 output plane everywhere (Q cols scaled by 0.125).
// ===========================================================================
#define H_OAH  0
#define H_OAL  10240
#define H_OB   20480
#define H_ST   33280
#define H_SMEM (2 * H_ST)   // 66560

__global__ __launch_bounds__(256)
void gemm_qkv(const uint16_t* __restrict__ Ah, const uint16_t* __restrict__ Al,
              const uint16_t* __restrict__ Bh,
              const float* __restrict__ bias,
              uint16_t* __restrict__ Ch,
              int N, int K, int qcols)
{
    extern __shared__ char sm[];
    const uint32_t sbase = smem_u32(sm);

    const int tid  = threadIdx.x;
    const int lane = tid & 31;
    const int wid  = tid >> 5;
    const int wm   = wid & 1;
    const int wn   = wid >> 1;
    const int row0 = blockIdx.y * 128;
    const int col0 = blockIdx.x * 192;

    const int ar = tid >> 1;
    const uint16_t* Aph = Ah + (size_t)(row0 + ar) * K + (tid & 1) * 16;
    const uint16_t* Apl = Al + (size_t)(row0 + ar) * K + (tid & 1) * 16;
    const uint32_t sao = (uint32_t)(ar * 80 + (tid & 1) * 32);
    const int br = tid >> 3;
    const uint16_t* Bp = Bh + (size_t)br * N + col0 + (tid & 7) * 8;
    const uint32_t sbo = (uint32_t)(br * 400 + (tid & 7) * 16);

    const int g  = lane >> 3;
    const int rr = lane & 7;
    uint32_t abase[4];
    #pragma unroll
    for (int mt = 0; mt < 4; mt++)
        abase[mt] = (uint32_t)((wm * 64 + mt * 16 + (g & 1) * 8 + rr) * 40
                               + (g >> 1) * 8) * 2u;
    uint32_t bbase[3];
    #pragma unroll
    for (int p = 0; p < 3; p++)
        bbase[p] = (uint32_t)(((g & 1) * 8 + rr) * 200
                              + wn * 48 + p * 16 + (g >> 1) * 8) * 2u;

    float acc[4][6][4];
    #pragma unroll
    for (int i = 0; i < 4; i++)
        #pragma unroll
        for (int j = 0; j < 6; j++)
            #pragma unroll
            for (int r = 0; r < 4; r++)
                acc[i][j][r] = 0.f;

    auto LOAD = [&](int st, int k0) {
        uint32_t s0 = sbase + st * H_ST;
        cp16(s0 + H_OAH + sao,      Aph + k0);
        cp16(s0 + H_OAH + sao + 16, Aph + k0 + 8);
        cp16(s0 + H_OAL + sao,      Apl + k0);
        cp16(s0 + H_OAL + sao + 16, Apl + k0 + 8);
        const uint16_t* b = Bp + (size_t)k0 * N;
        #pragma unroll
        for (int j = 0; j < 3; j++)
            cp16(s0 + H_OB + sbo + 128 * j, b + 64 * j);
    };

    const int nk = K / 32;
    LOAD(0, 0);
    cp_commit();

    for (int kc = 0; kc < nk; kc++) {
        cp_wait<0>();
        __syncthreads();
        if (kc + 1 < nk) { LOAD((kc + 1) & 1, (kc + 1) * 32); cp_commit(); }

        uint32_t s0 = sbase + (kc & 1) * H_ST;
        #pragma unroll
        for (int ks = 0; ks < 2; ks++) {
            const uint32_t ka = ks * 32u;
            const uint32_t kb = ks * 6400u;
            uint32_t ahi[4][4], alo[4][4];
            #pragma unroll
            for (int mt = 0; mt < 4; mt++) {
                ldsm_x4(ahi[mt], s0 + H_OAH + abase[mt] + ka);
                ldsm_x4(alo[mt], s0 + H_OAL + abase[mt] + ka);
            }
            uint32_t bf[3][4];
            #pragma unroll
            for (int p = 0; p < 3; p++)
                ldsm_x4_t(bf[p], s0 + H_OB + bbase[p] + kb);
            #pragma unroll
            for (int p = 0; p < 3; p++)
                #pragma unroll
                for (int mt = 0; mt < 4; mt++) {
                    mma_f16(acc[mt][2 * p + 0], ahi[mt], bf[p]);
                    mma_f16(acc[mt][2 * p + 1], ahi[mt], bf[p] + 2);
                }
            #pragma unroll
            for (int p = 0; p < 3; p++)
                #pragma unroll
                for (int mt = 0; mt < 4; mt++) {
                    mma_f16(acc[mt][2 * p + 0], alo[mt], bf[p]);
                    mma_f16(acc[mt][2 * p + 1], alo[mt], bf[p] + 2);
                }
        }
    }

    const int ml = lane >> 2;
    const int nl = 2 * (lane & 3);
    #pragma unroll
    for (int mt = 0; mt < 4; mt++) {
        #pragma unroll
        for (int nt = 0; nt < 6; nt++) {
            int m = row0 + wm * 64 + mt * 16 + ml;
            int n = col0 + wn * 48 + nt * 8 + nl;
            float2 bv = *(const float2*)&bias[n];
            float* c = acc[mt][nt];
            float sc = (n < qcols) ? 0.125f : 1.0f;
            *(uint32_t*)(Ch + (size_t)m * N + n) =
                pair_f16(make_float2((c[0] + bv.x) * sc, (c[1] + bv.y) * sc));
            *(uint32_t*)(Ch + (size_t)(m + 8) * N + n) =
                pair_f16(make_float2((c[2] + bv.x) * sc, (c[3] + bv.y) * sc));
        }
    }
}

// ===========================================================================
// Out-proj GEMM (unchanged from R16): 1-term fp16.
// ===========================================================================
#define G_OA   0
#define G_OB   10240
#define G_ST   18944
#define G_SMEM (2 * G_ST)   // 37888

__global__ __launch_bounds__(256, 2)
void gemm_out(const uint16_t* __restrict__ Ah,
              const uint16_t* __restrict__ Bh,
              const float* __restrict__ bias, float* __restrict__ Cf,
              int N, int K)
{
    extern __shared__ char sm[];
    const uint32_t sbase = smem_u32(sm);

    const int tid  = threadIdx.x;
    const int lane = tid & 31;
    const int wid  = tid >> 5;
    const int wm   = wid & 3;
    const int wn   = wid >> 2;
    const int row0 = blockIdx.y * 128;
    const int col0 = blockIdx.x * 128;

    const int ar  = tid >> 1;
    const int akc = (tid & 1) * 2;
    const int br  = tid >> 3;
    const int bnc = (tid & 7) * 2;

    const uint16_t* Ap = Ah + (size_t)(row0 + ar) * K + akc * 8;
    const uint16_t* Bp = Bh + (size_t)br * N + col0 + bnc * 8;

    const uint32_t sao0 = (uint32_t)(ar * 40 + akc * 8) * 2u;
    const uint32_t sao1 = sao0 + 16u;
    const uint32_t sbo0 = (uint32_t)(br * 136 + bnc * 8) * 2u;
    const uint32_t sbo1 = sbo0 + 16u;

    const int g  = lane >> 3;
    const int rr = lane & 7;
    uint32_t abase[2];
    #pragma unroll
    for (int mt = 0; mt < 2; mt++)
        abase[mt] = (uint32_t)((wm * 32 + mt * 16 + (g & 1) * 8 + rr) * 40
                               + (g >> 1) * 8) * 2u;
    uint32_t bbase[4];
    #pragma unroll
    for (int np = 0; np < 4; np++)
        bbase[np] = (uint32_t)(((g & 1) * 8 + rr) * 136
                               + wn * 64 + np * 16 + (g >> 1) * 8) * 2u;

    float acc[2][8][4];
    #pragma unroll
    for (int i = 0; i < 2; i++)
        #pragma unroll
        for (int j = 0; j < 8; j++)
            #pragma unroll
            for (int r = 0; r < 4; r++)
                acc[i][j][r] = 0.f;

    auto LOAD = [&](int st, int k0) {
        uint32_t s0 = sbase + st * G_ST;
        cp16(s0 + G_OA + sao0, Ap + k0);
        cp16(s0 + G_OA + sao1, Ap + k0 + 8);
        cp16(s0 + G_OB + sbo0, Bp + (size_t)k0 * N);
        cp16(s0 + G_OB + sbo1, Bp + (size_t)k0 * N + 8);
    };

    const int nk = K / 32;
    LOAD(0, 0);
    cp_commit();

    for (int kc = 0; kc < nk; kc++) {
        cp_wait<0>();
        __syncthreads();
        if (kc + 1 < nk) { LOAD((kc + 1) & 1, (kc + 1) * 32); cp_commit(); }

        uint32_t s0 = sbase + (kc & 1) * G_ST;
        #pragma unroll
        for (int ks = 0; ks < 2; ks++) {
            const uint32_t ka = ks * 32u;
            const uint32_t kb = ks * 4352u;
            uint32_t af[2][4];
            ldsm_x4(af[0], s0 + G_OA + abase[0] + ka);
            ldsm_x4(af[1], s0 + G_OA + abase[1] + ka);
            uint32_t bf[4][4];
            #pragma unroll
            for (int np = 0; np < 4; np++)
                ldsm_x4_t(bf[np], s0 + G_OB + bbase[np] + kb);
            #pragma unroll
            for (int np = 0; np < 4; np++)
                #pragma unroll
                for (int mt = 0; mt < 2; mt++) {
                    mma_f16(acc[mt][2 * np + 0], af[mt], bf[np]);
                    mma_f16(acc[mt][2 * np + 1], af[mt], bf[np] + 2);
                }
        }
    }

    const int ml = lane >> 2;
    const int nl = 2 * (lane & 3);
    #pragma unroll
    for (int mt = 0; mt < 2; mt++) {
        #pragma unroll
        for (int nt = 0; nt < 8; nt++) {
            int m = row0 + wm * 32 + mt * 16 + ml;
            int n = col0 + wn * 64 + nt * 8 + nl;
            float2 bv = *(const float2*)&bias[n];
            float* c = acc[mt][nt];
            *(float2*)(Cf + (size_t)m * N + n) =
                make_float2(c[0] + bv.x, c[1] + bv.y);
            *(float2*)(Cf + (size_t)(m + 8) * N + n) =
                make_float2(c[2] + bv.x, c[3] + bv.y);
        }
    }
}

// ===========================================================================
// Flash attention, R17: Q single fp16 (1-term QK), K/V single fp16,
// P single fp16. 64 HMMA/iter. smem 55296 B.
// ===========================================================================
#define FA_PAD  72
#define O_Q     0
#define KV_ST0  18432
#define P_K     0
#define P_V     9216
#define KV_STG  18432
#define FA_SMEM (KV_ST0 + 2 * KV_STG)   // 55296

__global__ __launch_bounds__(256)
void flash_attn_mma_kernel(const uint16_t* __restrict__ qkv,
                           uint16_t* __restrict__ attn)
{
    extern __shared__ char fsm[];
    const uint32_t sb = smem_u32(fsm);

    const int tid  = threadIdx.x;
    const int lane = tid & 31;
    const int wm   = tid >> 5;
    const int qt   = blockIdx.x;
    const int b    = blockIdx.y >> 4;
    const int h    = blockIdx.y & 15;

    // ---- load Q tile (single fp16, pre-scaled upstream) ----
    {
        const int r  = tid >> 1;
        const int c0 = (tid & 1) * 32;
        const uint16_t* q = qkv + (size_t)(b * SEQ + qt * 128 + r) * QKVW
                                + h * HD + c0;
        uint32_t base = (uint32_t)(r * FA_PAD + c0) * 2u;
        #pragma unroll
        for (int s = 0; s < 4; s++)
            *(uint4*)(fsm + O_Q + base + 16 * s) = *(const uint4*)(q + 8 * s);
    }

    const int kr  = tid >> 2;
    const int kc0 = (tid & 3) * 16;
    auto LOADKV = [&](int kt, int st) {
        size_t roff = (size_t)(b * SEQ + kt * 64 + kr) * QKVW + h * HD + kc0;
        const uint16_t* gk = qkv + roff + EMB;
        const uint16_t* gv = qkv + roff + 2 * EMB;
        uint32_t d = sb + KV_ST0 + (uint32_t)(st * KV_STG)
                   + (uint32_t)(kr * FA_PAD + kc0) * 2u;
        cp16(d + P_K,      gk);
        cp16(d + P_K + 16, gk + 8);
        cp16(d + P_V,      gv);
        cp16(d + P_V + 16, gv + 8);
    };

    LOADKV(0, 0);
    cp_commit();
    __syncthreads();

    // ---- preload Q fragments ----
    const int g  = lane >> 3;
    const int rr = lane & 7;
    uint32_t qf[4][4];
    {
        uint32_t moff = (uint32_t)((wm * 16 + (g & 1) * 8 + rr) * FA_PAD) * 2u;
        #pragma unroll
        for (int t = 0; t < 4; t++) {
            uint32_t koff = (uint32_t)((g >> 1) * 8 + 16 * t) * 2u;
            ldsm_x4(qf[t], sb + O_Q + moff + koff);
        }
    }

    const uint32_t kbase = (uint32_t)(((g >> 1) * 8 + rr) * FA_PAD + (g & 1) * 8) * 2u;
    const uint32_t vbase = (uint32_t)(((g & 1) * 8 + rr) * FA_PAD + (g >> 1) * 8) * 2u;

    float m0 = -1e30f, m1 = -1e30f, l0 = 0.f, l1 = 0.f;
    float o[8][4];
    #pragma unroll
    for (int j = 0; j < 8; j++)
        #pragma unroll
        for (int r = 0; r < 4; r++) o[j][r] = 0.f;

    for (int kt = 0; kt < SEQ / 64; kt++) {
        cp_wait<0>();
        __syncthreads();
        if (kt + 1 < SEQ / 64) { LOADKV(kt + 1, (kt + 1) & 1); cp_commit(); }

        const uint32_t stg = sb + KV_ST0 + (uint32_t)((kt & 1) * KV_STG);

        // ---- S = Q K^T : 1-term, term-major ----
        float s[8][4];
        #pragma unroll
        for (int j = 0; j < 8; j++)
            #pragma unroll
            for (int r4 = 0; r4 < 4; r4++) s[j][r4] = 0.f;

        #pragma unroll
        for (int t = 0; t < 4; t++) {
            uint32_t kf[4][4];
            #pragma unroll
            for (int nt = 0; nt < 4; nt++) {
                uint32_t off = kbase + (uint32_t)(nt * 16 * FA_PAD + 16 * t) * 2u;
                ldsm_x4(kf[nt], stg + P_K + off);
            }
            #pragma unroll
            for (int nt = 0; nt < 4; nt++) {
                mma_f16(s[2 * nt + 0], qf[t], kf[nt]);
                mma_f16(s[2 * nt + 1], qf[t], kf[nt] + 2);
            }
        }

        // ---- online softmax ----
        float mx0 = -1e30f, mx1 = -1e30f;
        #pragma unroll
        for (int j = 0; j < 8; j++) {
            mx0 = fmaxf(mx0, fmaxf(s[j][0], s[j][1]));
            mx1 = fmaxf(mx1, fmaxf(s[j][2], s[j][3]));
        }
        mx0 = fmaxf(mx0, __shfl_xor_sync(0xffffffffu, mx0, 1));
        mx0 = fmaxf(mx0, __shfl_xor_sync(0xffffffffu, mx0, 2));
        mx1 = fmaxf(mx1, __shfl_xor_sync(0xffffffffu, mx1, 1));
        mx1 = fmaxf(mx1, __shfl_xor_sync(0xffffffffu, mx1, 2));

        float mn0 = fmaxf(m0, mx0), mn1 = fmaxf(m1, mx1);
        float a0 = __expf(m0 - mn0), a1 = __expf(m1 - mn1);
        m0 = mn0; m1 = mn1;

        float sum0 = 0.f, sum1 = 0.f;
        #pragma unroll
        for (int j = 0; j < 8; j++) {
            s[j][0] = __expf(s[j][0] - mn0);
            s[j][1] = __expf(s[j][1] - mn0);
            s[j][2] = __expf(s[j][2] - mn1);
            s[j][3] = __expf(s[j][3] - mn1);
            sum0 += s[j][0] + s[j][1];
            sum1 += s[j][2] + s[j][3];
        }
        sum0 += __shfl_xor_sync(0xffffffffu, sum0, 1);
        sum0 += __shfl_xor_sync(0xffffffffu, sum0, 2);
        sum1 += __shfl_xor_sync(0xffffffffu, sum1, 1);
        sum1 += __shfl_xor_sync(0xffffffffu, sum1, 2);
        l0 = l0 * a0 + sum0;
        l1 = l1 * a1 + sum1;

        #pragma unroll
        for (int j = 0; j < 8; j++) {
            o[j][0] *= a0; o[j][1] *= a0;
            o[j][2] *= a1; o[j][3] *= a1;
        }

        // ---- o += P V : single-term fp16 P, term-major ----
        #pragma unroll
        for (int t = 0; t < 4; t++) {
            uint32_t pf[4];
            pf[0] = pair_f16(make_float2(s[2*t][0],   s[2*t][1]));
            pf[1] = pair_f16(make_float2(s[2*t][2],   s[2*t][3]));
            pf[2] = pair_f16(make_float2(s[2*t+1][0], s[2*t+1][1]));
            pf[3] = pair_f16(make_float2(s[2*t+1][2], s[2*t+1][3]));
            uint32_t vf[4][4];
            #pragma unroll
            for (int nt = 0; nt < 4; nt++) {
                uint32_t off = vbase + (uint32_t)(t * 16 * FA_PAD + nt * 16) * 2u;
                ldsm_x4_t(vf[nt], stg + P_V + off);
            }
            #pragma unroll
            for (int nt = 0; nt < 4; nt++) {
                mma_f16(o[2 * nt + 0], pf, vf[nt]);
                mma_f16(o[2 * nt + 1], pf, vf[nt] + 2);
            }
        }
    }

    // ---- epilogue: normalize, single rn-f16 plane ----
    float inv0 = 1.f / l0, inv1 = 1.f / l1;
    int row = b * SEQ + qt * 128 + wm * 16 + (lane >> 2);
    size_t e0 = (size_t)row * EMB + h * HD + 2 * (lane & 3);
    #pragma unroll
    for (int j = 0; j < 8; j++) {
        *(uint32_t*)(attn + e0 + 8 * j) =
            pair_f16(make_float2(o[j][0] * inv0, o[j][1] * inv0));
        *(uint32_t*)(attn + e0 + (size_t)8 * EMB + 8 * j) =
            pair_f16(make_float2(o[j][2] * inv1, o[j][3] * inv1));
    }
}

// ---------------------------------------------------------------------------
extern "C" void kernel_launch(void* const* d_in, const int* in_sizes, int n_in,
                              void* d_out, int out_size)
{
    (void)in_sizes; (void)n_in; (void)out_size;
    const float* x     = (const float*)d_in[0];
    const float* w_qkv = (const float*)d_in[1];
    const float* b_qkv = (const float*)d_in[2];
    const float* w_out = (const float*)d_in[3];
    const float* b_out = (const float*)d_in[4];
    float* out = (float*)d_out;

    uint16_t *x_hi, *x_lo, *wq, *wo, *qkv, *attn;
    cudaGetSymbolAddress((void**)&x_hi, g_x_hi);
    cudaGetSymbolAddress((void**)&x_lo, g_x_lo);
    cudaGetSymbolAddress((void**)&wq,   g_wqkv);
    cudaGetSymbolAddress((void**)&wo,   g_wout);
    cudaGetSymbolAddress((void**)&qkv,  g_qkv);
    cudaGetSymbolAddress((void**)&attn, g_attn);

    cudaFuncSetAttribute(gemm_qkv,
                         cudaFuncAttributeMaxDynamicSharedMemorySize, H_SMEM);
    cudaFuncSetAttribute(gemm_out,
                         cudaFuncAttributeMaxDynamicSharedMemorySize, G_SMEM);
    cudaFuncSetAttribute(flash_attn_mma_kernel,
                         cudaFuncAttributeMaxDynamicSharedMemorySize, FA_SMEM);

    // 0) merged converts
    const int n4_total = N4_X + N4_WQ + N4_WO;
    split_all_kernel<<<(n4_total + 255) / 256, 256>>>(
        (const float4*)x, (const float4*)w_qkv, (const float4*)w_out,
        x_hi, x_lo, wq, wo);

    // 1) QKV projection (2-term fp16) -> single fp16 plane (Q pre-scaled)
    gemm_qkv<<<dim3(QKVW / 192, NROWS / 128), 256, H_SMEM>>>(
        x_hi, x_lo, wq, b_qkv, qkv, QKVW, EMB, EMB);

    // 2) attention (QK 1-term, PV 1-term) -> single fp16 plane
    flash_attn_mma_kernel<<<dim3(SEQ / 128, BATCH * HEADS), 256, FA_SMEM>>>(
        qkv, attn);

    // 3) output projection (1-term fp16) -> fp32 out
    gemm_out<<<dim3(EMB / 128, NROWS / 128), 256, G_SMEM>>>(
        attn, wo, b_out, out, EMB, EMB);
}